// round 4
// baseline (speedup 1.0000x reference)
#include <cuda_runtime.h>
#include <cstdint>
#include <math.h>

#define NN 100000
#define EE 1600000
#define RS 68              // padded smem row stride (floats)
#define ETILE 64           // edges per CTA tile
#define NTILE 64           // nodes per CTA tile

// ---------------- device scratch ----------------
__device__ float g_asrc[NN * 64];
__device__ float g_adst[NN * 64];
__device__ float g_v[NN * 64];
__device__ float g_num[NN * 64];
__device__ float g_den[NN * 64];

// ---------------- helpers ----------------
__device__ __forceinline__ void red_add4(float* p, float4 v) {
    asm volatile("red.global.add.v4.f32 [%0], {%1,%2,%3,%4};"
                 :: "l"(p), "f"(v.x), "f"(v.y), "f"(v.z), "f"(v.w) : "memory");
}
__device__ __forceinline__ float to_tf32(float x) {
    unsigned u;
    asm("cvt.rna.tf32.f32 %0, %1;" : "=r"(u) : "f"(x));
    return __uint_as_float(u);
}
__device__ __forceinline__ void mma_tf32(float c[4], unsigned a0, unsigned a1,
                                         unsigned a2, unsigned a3,
                                         unsigned b0, unsigned b1) {
    asm volatile(
        "mma.sync.aligned.m16n8k8.row.col.f32.tf32.tf32.f32 "
        "{%0,%1,%2,%3},{%4,%5,%6,%7},{%8,%9},{%0,%1,%2,%3};"
        : "+f"(c[0]), "+f"(c[1]), "+f"(c[2]), "+f"(c[3])
        : "r"(a0), "r"(a1), "r"(a2), "r"(a3), "r"(b0), "r"(b1));
}

// GEMM: acc[NT][4] += bufIn[rows 16 @rbase] @ WT  (cols NT*8 @ n0base)
template<int NT>
__device__ __forceinline__ void gemm_tile(const float* __restrict__ bufIn,
                                          const float* __restrict__ WT,
                                          int rbase, int n0base, int lane,
                                          float acc[NT][4]) {
    int r = lane >> 2, c = lane & 3;
    const float* a0p = bufIn + (rbase + r) * RS + c;
    const float* a1p = a0p + 8 * RS;
#pragma unroll
    for (int k0 = 0; k0 < 64; k0 += 8) {
        unsigned a0 = __float_as_uint(a0p[k0]);
        unsigned a1 = __float_as_uint(a1p[k0]);
        unsigned a2 = __float_as_uint(a0p[k0 + 4]);
        unsigned a3 = __float_as_uint(a1p[k0 + 4]);
#pragma unroll
        for (int nt = 0; nt < NT; nt++) {
            const float* bp = WT + (size_t)(n0base + nt * 8 + r) * RS + k0 + c;
            unsigned b0 = __float_as_uint(bp[0]);
            unsigned b1 = __float_as_uint(bp[4]);
            mma_tf32(acc[nt], a0, a1, a2, a3, b0, b1);
        }
    }
}

template<int NT>
__device__ __forceinline__ void zero_acc(float acc[NT][4]) {
#pragma unroll
    for (int nt = 0; nt < NT; nt++)
#pragma unroll
        for (int j = 0; j < 4; j++) acc[nt][j] = 0.f;
}

template<int NT, int MODE>   // MODE 0: tf32(relu(+b)); MODE 1: exp(relu(+b))
__device__ __forceinline__ void frag_store(float* __restrict__ bufOut,
                                           const float* __restrict__ bias,
                                           int rbase, int n0base, int lane,
                                           float acc[NT][4]) {
    int r0 = rbase + (lane >> 2);
#pragma unroll
    for (int nt = 0; nt < NT; nt++) {
        int col = n0base + nt * 8 + 2 * (lane & 3);
        float2 b = *(const float2*)&bias[col];
        float v00 = fmaxf(acc[nt][0] + b.x, 0.f);
        float v01 = fmaxf(acc[nt][1] + b.y, 0.f);
        float v10 = fmaxf(acc[nt][2] + b.x, 0.f);
        float v11 = fmaxf(acc[nt][3] + b.y, 0.f);
        if (MODE == 0) {
            v00 = to_tf32(v00); v01 = to_tf32(v01);
            v10 = to_tf32(v10); v11 = to_tf32(v11);
        } else {
            v00 = __expf(v00); v01 = __expf(v01);
            v10 = __expf(v10); v11 = __expf(v11);
        }
        *(float2*)&bufOut[(size_t)r0 * RS + col] = make_float2(v00, v01);
        *(float2*)&bufOut[(size_t)(r0 + 8) * RS + col] = make_float2(v10, v11);
    }
}

// ---------------- init ----------------
__global__ void zero_kernel() {
    int i = blockIdx.x * blockDim.x + threadIdx.x;
    int stride = gridDim.x * blockDim.x;
    float4 z = make_float4(0.f, 0.f, 0.f, 0.f);
    for (; i < NN * 64 / 4; i += stride) {
        ((float4*)g_num)[i] = z;
        ((float4*)g_den)[i] = z;
    }
}

// ============================================================================
// node_prep (256 thr, 64-node tiles, 2 CTAs/SM)
// ============================================================================
__global__ void __launch_bounds__(256) node_prep(
    const float* __restrict__ x,
    const float* __restrict__ W_in, const float* __restrict__ b_in,
    const float* __restrict__ W_lin, const float* __restrict__ W_src,
    const float* __restrict__ W_dst)
{
    extern __shared__ float sm[];
    float* WinT = sm;              // 4352
    float* WsT  = sm + 4352;
    float* WdT  = sm + 8704;
    float* WlT  = sm + 13056;
    float* bin  = sm + 17408;      // 64
    float* bufA = sm + 17472;      // 4352 (64*68)
    float* bufB = sm + 21824;      // 4352 -> total 26176 floats (102.25 KB)

    int t = threadIdx.x;
    for (int i = t; i < 4096; i += 256) {
        int k = i >> 6, n = i & 63;
        WinT[n * RS + k] = to_tf32(W_in[i]);
        WsT[n * RS + k]  = to_tf32(W_src[i]);
        WdT[n * RS + k]  = to_tf32(W_dst[i]);
        WlT[n * RS + k]  = to_tf32(W_lin[i]);
    }
    if (t < 64) bin[t] = b_in[t];
    __syncthreads();

    int w = t >> 5, lane = t & 31;
    int rbase = (w & 3) * 16;       // 4 M-groups of 16 rows
    int n0base = (w >> 2) * 32;     // 2 N-halves
    int ntiles = (NN + NTILE - 1) / NTILE;

    for (int tile = blockIdx.x; tile < ntiles; tile += gridDim.x) {
        int base = tile * NTILE;
        __syncthreads();
        // stage x (tf32), zero tail
#pragma unroll
        for (int rr = 0; rr < 4; rr++) {
            int i = t + 256 * rr;              // float4 index
            int row = i >> 4, col = (i & 15) * 4;
            int n = base + row;
            float4 v = make_float4(0, 0, 0, 0);
            if (n < NN) {
                v = *(const float4*)&x[(size_t)n * 64 + col];
                v.x = to_tf32(v.x); v.y = to_tf32(v.y);
                v.z = to_tf32(v.z); v.w = to_tf32(v.w);
            }
            *(float4*)&bufA[(size_t)row * RS + col] = v;
        }
        __syncthreads();

        // h = relu(x@W_in + b) -> bufB (tf32)
        {
            float acc[4][4];
            zero_acc<4>(acc);
            gemm_tile<4>(bufA, WinT, rbase, n0base, lane, acc);
            frag_store<4, 0>(bufB, bin, rbase, n0base, lane, acc);
        }
        __syncthreads();

        // three output GEMMs -> global
        const float* WTs[3] = {WsT, WdT, WlT};
        float* outs[3] = {g_asrc, g_adst, g_v};
#pragma unroll
        for (int p = 0; p < 3; p++) {
            float acc[4][4];
            zero_acc<4>(acc);
            gemm_tile<4>(bufB, WTs[p], rbase, n0base, lane, acc);
            int n0r = base + rbase + (lane >> 2);
#pragma unroll
            for (int nt = 0; nt < 4; nt++) {
                int col = n0base + nt * 8 + 2 * (lane & 3);
                if (n0r < NN)
                    *(float2*)&outs[p][(size_t)n0r * 64 + col] =
                        make_float2(acc[nt][0], acc[nt][1]);
                if (n0r + 8 < NN)
                    *(float2*)&outs[p][(size_t)(n0r + 8) * 64 + col] =
                        make_float2(acc[nt][2], acc[nt][3]);
            }
        }
    }
}

// ============================================================================
// edge kernel (256 thr, 64-edge tiles, 2 CTAs/SM)
// ============================================================================
__global__ void __launch_bounds__(256) edge_kernel(
    const float* __restrict__ pos,
    const int* __restrict__ src, const int* __restrict__ dst,
    const float* __restrict__ posw1, const float* __restrict__ posb1,
    const float* __restrict__ posw2, const float* __restrict__ posb2,
    const float* __restrict__ attw1, const float* __restrict__ attb1,
    const float* __restrict__ attw2, const float* __restrict__ attb2)
{
    extern __shared__ float sm[];
    float* sw1  = sm;              // 192
    float* sb1  = sm + 192;
    float* sb2  = sm + 256;
    float* sab1 = sm + 320;
    float* sab2 = sm + 384;        // -> 448
    float* wp2T = sm + 448;        // 4352
    float* wa1T = sm + 4800;       // 4352
    float* wa2T = sm + 9152;       // 4352 -> 13504
    float* dpos = sm + 13504;      // 192
    float* bufA = sm + 13696;      // 4352
    float* bufB = sm + 18048;      // 4352
    float* bufD = sm + 22400;      // 4352 -> 26752
    int*   sidx = (int*)(sm + 26752);  // 64
    int*   didx = (int*)(sm + 26816);  // 64 -> total 26880 floats (105 KB)

    int t = threadIdx.x;
    for (int i = t; i < 4096; i += 256) {
        int k = i >> 6, n = i & 63;
        wp2T[n * RS + k] = to_tf32(posw2[i]);
        wa1T[n * RS + k] = to_tf32(attw1[i]);
        wa2T[n * RS + k] = to_tf32(attw2[i]);
    }
    if (t < 192) sw1[t] = posw1[t];
    if (t < 64) { sb1[t] = posb1[t]; sb2[t] = posb2[t];
                  sab1[t] = attb1[t]; sab2[t] = attb2[t]; }
    __syncthreads();

    int w = t >> 5, lane = t & 31;
    int rbase = (w & 3) * 16;       // 4 M-groups (64 edges)
    int n0base = (w >> 2) * 32;     // 2 N-halves
    int cg = t & 3, c0 = cg * 16;   // scalar-phase mapping
    int el = t >> 2;                // local edge 0..63
    const int ntiles = EE / ETILE;  // 25000

    for (int tile = blockIdx.x; tile < ntiles; tile += gridDim.x) {
        __syncthreads();
        // ---- stage indices + pos deltas ----
        if (t < ETILE) {
            int e = tile * ETILE + t;
            int s = src[e], d = dst[e];
            sidx[t] = s; didx[t] = d;
            dpos[t * 3 + 0] = pos[d * 3 + 0] - pos[s * 3 + 0];
            dpos[t * 3 + 1] = pos[d * 3 + 1] - pos[s * 3 + 1];
            dpos[t * 3 + 2] = pos[d * 3 + 2] - pos[s * 3 + 2];
        }
        __syncthreads();

        // ---- layer 1 (K=3, scalar): h1 -> bufA (tf32) ----
        {
            float p0 = dpos[el * 3 + 0], p1 = dpos[el * 3 + 1], p2 = dpos[el * 3 + 2];
#pragma unroll
            for (int j = 0; j < 4; j++) {
                int col = c0 + 4 * j;
                float4 b = *(float4*)&sb1[col];
                float4 w0 = *(float4*)&sw1[col];
                float4 w1r = *(float4*)&sw1[64 + col];
                float4 w2r = *(float4*)&sw1[128 + col];
                float4 a;
                a.x = fmaxf(fmaf(p2, w2r.x, fmaf(p1, w1r.x, fmaf(p0, w0.x, b.x))), 0.f);
                a.y = fmaxf(fmaf(p2, w2r.y, fmaf(p1, w1r.y, fmaf(p0, w0.y, b.y))), 0.f);
                a.z = fmaxf(fmaf(p2, w2r.z, fmaf(p1, w1r.z, fmaf(p0, w0.z, b.z))), 0.f);
                a.w = fmaxf(fmaf(p2, w2r.w, fmaf(p1, w1r.w, fmaf(p0, w0.w, b.w))), 0.f);
                a.x = to_tf32(a.x); a.y = to_tf32(a.y);
                a.z = to_tf32(a.z); a.w = to_tf32(a.w);
                *(float4*)&bufA[(size_t)el * RS + col] = a;
            }
        }
        __syncthreads();

        // ---- layer 2 (MMA): delta = relu(h1@posW2+b2) -> bufD (tf32) ----
        {
            float acc[4][4];
            zero_acc<4>(acc);
            gemm_tile<4>(bufA, wp2T, rbase, n0base, lane, acc);
            frag_store<4, 0>(bufD, sb2, rbase, n0base, lane, acc);
        }
        __syncthreads();

        // ---- gather: t = tf32(adst[d]-asrc[s]+delta) -> bufB ----
        {
            int s = sidx[el], d = didx[el];
            const float4* ad = (const float4*)&g_adst[(size_t)d * 64 + c0];
            const float4* as = (const float4*)&g_asrc[(size_t)s * 64 + c0];
#pragma unroll
            for (int j = 0; j < 4; j++) {
                float4 A = ad[j], S = as[j];
                float4 D = *(float4*)&bufD[(size_t)el * RS + c0 + 4 * j];
                float4 tv;
                tv.x = to_tf32(A.x - S.x + D.x);
                tv.y = to_tf32(A.y - S.y + D.y);
                tv.z = to_tf32(A.z - S.z + D.z);
                tv.w = to_tf32(A.w - S.w + D.w);
                *(float4*)&bufB[(size_t)el * RS + c0 + 4 * j] = tv;
            }
        }
        __syncthreads();

        // ---- layer 3 (MMA): h2 = relu(t@attW1+b1) -> bufA (tf32) ----
        {
            float acc[4][4];
            zero_acc<4>(acc);
            gemm_tile<4>(bufB, wa1T, rbase, n0base, lane, acc);
            frag_store<4, 0>(bufA, sab1, rbase, n0base, lane, acc);
        }
        __syncthreads();

        // ---- layer 4 (MMA): ex = exp(relu(h2@attW2+b2)) -> bufB (fp32) ----
        {
            float acc[4][4];
            zero_acc<4>(acc);
            gemm_tile<4>(bufA, wa2T, rbase, n0base, lane, acc);
            frag_store<4, 1>(bufB, sab2, rbase, n0base, lane, acc);
        }
        __syncthreads();

        // ---- scatter: num += ex*(v[s]+delta); den += ex ----
        {
            int s = sidx[el], d = didx[el];
            float* nump = &g_num[(size_t)d * 64 + c0];
            float* denp = &g_den[(size_t)d * 64 + c0];
            const float4* vv = (const float4*)&g_v[(size_t)s * 64 + c0];
#pragma unroll
            for (int j = 0; j < 4; j++) {
                float4 ex = *(float4*)&bufB[(size_t)el * RS + c0 + 4 * j];
                float4 D  = *(float4*)&bufD[(size_t)el * RS + c0 + 4 * j];
                float4 V  = vv[j];
                float4 m;
                m.x = ex.x * (V.x + D.x); m.y = ex.y * (V.y + D.y);
                m.z = ex.z * (V.z + D.z); m.w = ex.w * (V.w + D.w);
                red_add4(nump + 4 * j, m);
                red_add4(denp + 4 * j, ex);
            }
        }
    }
}

// ============================================================================
// final (256 thr): out = relu((num/den)@W_out + b_out)
// ============================================================================
__global__ void __launch_bounds__(256) final_kernel(
    const float* __restrict__ W_out, const float* __restrict__ b_out,
    float* __restrict__ out)
{
    extern __shared__ float sm[];
    float* WoT  = sm;              // 4352
    float* bo   = sm + 4352;       // 64
    float* bufA = sm + 4416;       // 8704 -> total 13120 floats

    int t = threadIdx.x;
    for (int i = t; i < 4096; i += 256) {
        int k = i >> 6, n = i & 63;
        WoT[n * RS + k] = to_tf32(W_out[i]);
    }
    if (t < 64) bo[t] = b_out[t];
    __syncthreads();

    int w = t >> 5, lane = t & 31;
    int rbase = w * 16;
    int ntiles = (NN + 127) / 128;

    for (int tile = blockIdx.x; tile < ntiles; tile += gridDim.x) {
        int base = tile * 128;
        __syncthreads();
#pragma unroll
        for (int rr = 0; rr < 8; rr++) {
            int i = t + 256 * rr;
            int row = i >> 4, col = (i & 15) * 4;
            int n = base + row;
            float4 v = make_float4(0, 0, 0, 0);
            if (n < NN) {
                float4 nu = *(const float4*)&g_num[(size_t)n * 64 + col];
                float4 de = *(const float4*)&g_den[(size_t)n * 64 + col];
                v.x = to_tf32(nu.x / (de.x + 1e-16f));
                v.y = to_tf32(nu.y / (de.y + 1e-16f));
                v.z = to_tf32(nu.z / (de.z + 1e-16f));
                v.w = to_tf32(nu.w / (de.w + 1e-16f));
            }
            *(float4*)&bufA[(size_t)row * RS + col] = v;
        }
        __syncthreads();

        float acc[8][4];
        zero_acc<8>(acc);
        gemm_tile<8>(bufA, WoT, rbase, 0, lane, acc);

        int n0r = base + rbase + (lane >> 2);
#pragma unroll
        for (int nt = 0; nt < 8; nt++) {
            int col = nt * 8 + 2 * (lane & 3);
            float2 b = *(const float2*)&bo[col];
            if (n0r < NN)
                *(float2*)&out[(size_t)n0r * 64 + col] =
                    make_float2(fmaxf(acc[nt][0] + b.x, 0.f),
                                fmaxf(acc[nt][1] + b.y, 0.f));
            if (n0r + 8 < NN)
                *(float2*)&out[(size_t)(n0r + 8) * 64 + col] =
                    make_float2(fmaxf(acc[nt][2] + b.x, 0.f),
                                fmaxf(acc[nt][3] + b.y, 0.f));
        }
    }
}

// ---------------- launch ----------------
extern "C" void kernel_launch(void* const* d_in, const int* in_sizes, int n_in,
                              void* d_out, int out_size)
{
    const float* x      = (const float*)d_in[0];
    const float* pos    = (const float*)d_in[1];
    const int*   ei     = (const int*)d_in[2];
    const float* W_in   = (const float*)d_in[3];
    const float* b_in   = (const float*)d_in[4];
    const float* W_out  = (const float*)d_in[5];
    const float* b_out  = (const float*)d_in[6];
    const float* W_lin  = (const float*)d_in[7];
    const float* W_src  = (const float*)d_in[8];
    const float* W_dst  = (const float*)d_in[9];
    const float* posw1  = (const float*)d_in[10];
    const float* posb1  = (const float*)d_in[11];
    const float* posw2  = (const float*)d_in[12];
    const float* posb2  = (const float*)d_in[13];
    const float* attw1  = (const float*)d_in[14];
    const float* attb1  = (const float*)d_in[15];
    const float* attw2  = (const float*)d_in[16];
    const float* attb2  = (const float*)d_in[17];
    float* out = (float*)d_out;

    const int NP_SMEM = 26176 * 4;   // 102.25 KB -> 2 CTAs/SM
    const int EK_SMEM = 26880 * 4;   // 105 KB    -> 2 CTAs/SM
    const int FN_SMEM = 13120 * 4;
    cudaFuncSetAttribute(node_prep, cudaFuncAttributeMaxDynamicSharedMemorySize, NP_SMEM);
    cudaFuncSetAttribute(edge_kernel, cudaFuncAttributeMaxDynamicSharedMemorySize, EK_SMEM);
    cudaFuncSetAttribute(final_kernel, cudaFuncAttributeMaxDynamicSharedMemorySize, FN_SMEM);

    zero_kernel<<<1024, 256>>>();
    node_prep<<<296, 256, NP_SMEM>>>(x, W_in, b_in, W_lin, W_src, W_dst);
    edge_kernel<<<296, 256, EK_SMEM>>>(pos, ei, ei + EE,
                                       posw1, posb1, posw2, posb2,
                                       attw1, attb1, attw2, attb2);
    final_kernel<<<444, 256, FN_SMEM>>>(W_out, b_out, out);
}

// round 5
// speedup vs baseline: 1.1260x; 1.1260x over previous
#include <cuda_runtime.h>
#include <cstdint>
#include <math.h>

#define NN 100000
#define EE 1600000
#define RS 68              // padded smem row stride (floats)

// ---------------- device scratch ----------------
__device__ float g_asrc[NN * 64];
__device__ float g_adst[NN * 64];
__device__ float g_v[NN * 64];
__device__ float g_num[NN * 64];
__device__ float g_den[NN * 64];

// ---------------- helpers ----------------
__device__ __forceinline__ void red_add4(float* p, float4 v) {
    asm volatile("red.global.add.v4.f32 [%0], {%1,%2,%3,%4};"
                 :: "l"(p), "f"(v.x), "f"(v.y), "f"(v.z), "f"(v.w) : "memory");
}
__device__ __forceinline__ float to_tf32(float x) {
    unsigned u;
    asm("cvt.rna.tf32.f32 %0, %1;" : "=r"(u) : "f"(x));
    return __uint_as_float(u);
}
__device__ __forceinline__ void mma_tf32(float c[4], unsigned a0, unsigned a1,
                                         unsigned a2, unsigned a3,
                                         unsigned b0, unsigned b1) {
    asm volatile(
        "mma.sync.aligned.m16n8k8.row.col.f32.tf32.tf32.f32 "
        "{%0,%1,%2,%3},{%4,%5,%6,%7},{%8,%9},{%0,%1,%2,%3};"
        : "+f"(c[0]), "+f"(c[1]), "+f"(c[2]), "+f"(c[3])
        : "r"(a0), "r"(a1), "r"(a2), "r"(a3), "r"(b0), "r"(b1));
}
__device__ __forceinline__ void ldsm4(unsigned addr, unsigned& r0, unsigned& r1,
                                      unsigned& r2, unsigned& r3) {
    asm volatile("ldmatrix.sync.aligned.m8n8.x4.shared.b16 {%0,%1,%2,%3}, [%4];"
                 : "=r"(r0), "=r"(r1), "=r"(r2), "=r"(r3) : "r"(addr));
}

// ---- scalar-LDS GEMM (node_prep / final, unchanged from R3) ----
template<int NT>
__device__ __forceinline__ void gemm_tile(const float* __restrict__ bufIn,
                                          const float* __restrict__ WT,
                                          int rbase, int n0base, int lane,
                                          float acc[NT][4]) {
    int r = lane >> 2, c = lane & 3;
    const float* a0p = bufIn + (rbase + r) * RS + c;
    const float* a1p = a0p + 8 * RS;
#pragma unroll
    for (int k0 = 0; k0 < 64; k0 += 8) {
        unsigned a0 = __float_as_uint(a0p[k0]);
        unsigned a1 = __float_as_uint(a1p[k0]);
        unsigned a2 = __float_as_uint(a0p[k0 + 4]);
        unsigned a3 = __float_as_uint(a1p[k0 + 4]);
#pragma unroll
        for (int nt = 0; nt < NT; nt++) {
            const float* bp = WT + (size_t)(n0base + nt * 8 + r) * RS + k0 + c;
            unsigned b0 = __float_as_uint(bp[0]);
            unsigned b1 = __float_as_uint(bp[4]);
            mma_tf32(acc[nt], a0, a1, a2, a3, b0, b1);
        }
    }
}

// ---- ldmatrix GEMM (edge kernel). NT must be even. ----
template<int NT>
__device__ __forceinline__ void gemm_ldsm(const float* __restrict__ buf,
                                          const float* __restrict__ WT,
                                          int rbase, int n0base, int lane,
                                          float acc[NT][4]) {
    unsigned aA = (unsigned)__cvta_generic_to_shared(
        buf + (rbase + (lane & 15)) * RS + ((lane >> 4) << 2));
    unsigned bA = (unsigned)__cvta_generic_to_shared(
        WT + (n0base + (lane & 7) + ((lane & 16) >> 1)) * RS + ((lane & 8) ? 4 : 0));
#pragma unroll
    for (int k0 = 0; k0 < 64; k0 += 8) {
        unsigned a0, a1, a2, a3;
        ldsm4(aA + k0 * 4, a0, a1, a2, a3);
#pragma unroll
        for (int p = 0; p < NT / 2; p++) {
            unsigned b0, b1, b2, b3;
            ldsm4(bA + (unsigned)(p * 16 * RS + k0) * 4, b0, b1, b2, b3);
            mma_tf32(acc[2 * p],     a0, a1, a2, a3, b0, b1);
            mma_tf32(acc[2 * p + 1], a0, a1, a2, a3, b2, b3);
        }
    }
}

template<int NT>
__device__ __forceinline__ void zero_acc(float acc[NT][4]) {
#pragma unroll
    for (int nt = 0; nt < NT; nt++)
#pragma unroll
        for (int j = 0; j < 4; j++) acc[nt][j] = 0.f;
}

template<int NT, int MODE>   // MODE 0: tf32(relu(+b)); MODE 1: exp(relu(+b))
__device__ __forceinline__ void frag_store(float* __restrict__ bufOut,
                                           const float* __restrict__ bias,
                                           int rbase, int n0base, int lane,
                                           float acc[NT][4]) {
    int r0 = rbase + (lane >> 2);
#pragma unroll
    for (int nt = 0; nt < NT; nt++) {
        int col = n0base + nt * 8 + 2 * (lane & 3);
        float2 b = *(const float2*)&bias[col];
        float v00 = fmaxf(acc[nt][0] + b.x, 0.f);
        float v01 = fmaxf(acc[nt][1] + b.y, 0.f);
        float v10 = fmaxf(acc[nt][2] + b.x, 0.f);
        float v11 = fmaxf(acc[nt][3] + b.y, 0.f);
        if (MODE == 0) {
            v00 = to_tf32(v00); v01 = to_tf32(v01);
            v10 = to_tf32(v10); v11 = to_tf32(v11);
        } else {
            v00 = __expf(v00); v01 = __expf(v01);
            v10 = __expf(v10); v11 = __expf(v11);
        }
        *(float2*)&bufOut[(size_t)r0 * RS + col] = make_float2(v00, v01);
        *(float2*)&bufOut[(size_t)(r0 + 8) * RS + col] = make_float2(v10, v11);
    }
}

// ---------------- init ----------------
__global__ void zero_kernel() {
    int i = blockIdx.x * blockDim.x + threadIdx.x;
    int stride = gridDim.x * blockDim.x;
    float4 z = make_float4(0.f, 0.f, 0.f, 0.f);
    for (; i < NN * 64 / 4; i += stride) {
        ((float4*)g_num)[i] = z;
        ((float4*)g_den)[i] = z;
    }
}

// ============================================================================
// node_prep (256 thr, 128-node tiles) — R3 version
// ============================================================================
__global__ void __launch_bounds__(256) node_prep(
    const float* __restrict__ x,
    const float* __restrict__ W_in, const float* __restrict__ b_in,
    const float* __restrict__ W_lin, const float* __restrict__ W_src,
    const float* __restrict__ W_dst)
{
    extern __shared__ float sm[];
    float* WinT = sm;              // 4352
    float* WsT  = sm + 4352;
    float* WdT  = sm + 8704;
    float* WlT  = sm + 13056;
    float* bin  = sm + 17408;      // 64
    float* bufA = sm + 17472;      // 8704
    float* bufB = sm + 26176;      // 8704 -> 34880 floats

    int t = threadIdx.x;
    for (int i = t; i < 4096; i += 256) {
        int k = i >> 6, n = i & 63;
        WinT[n * RS + k] = to_tf32(W_in[i]);
        WsT[n * RS + k]  = to_tf32(W_src[i]);
        WdT[n * RS + k]  = to_tf32(W_dst[i]);
        WlT[n * RS + k]  = to_tf32(W_lin[i]);
    }
    if (t < 64) bin[t] = b_in[t];
    __syncthreads();

    int w = t >> 5, lane = t & 31;
    int rbase = w * 16;
    int ntiles = (NN + 127) / 128;

    for (int tile = blockIdx.x; tile < ntiles; tile += gridDim.x) {
        int base = tile * 128;
        __syncthreads();
#pragma unroll
        for (int rr = 0; rr < 8; rr++) {
            int i = t + 256 * rr;
            int row = i >> 4, col = (i & 15) * 4;
            int n = base + row;
            float4 v = make_float4(0, 0, 0, 0);
            if (n < NN) {
                v = *(const float4*)&x[(size_t)n * 64 + col];
                v.x = to_tf32(v.x); v.y = to_tf32(v.y);
                v.z = to_tf32(v.z); v.w = to_tf32(v.w);
            }
            *(float4*)&bufA[(size_t)row * RS + col] = v;
        }
        __syncthreads();

        {
            float acc[8][4];
            zero_acc<8>(acc);
            gemm_ldsm<8>(bufA, WinT, rbase, 0, lane, acc);
            frag_store<8, 0>(bufB, bin, rbase, 0, lane, acc);
        }
        __syncthreads();

        const float* WTs[3] = {WsT, WdT, WlT};
        float* outs[3] = {g_asrc, g_adst, g_v};
#pragma unroll
        for (int p = 0; p < 3; p++) {
            float acc[8][4];
            zero_acc<8>(acc);
            gemm_ldsm<8>(bufB, WTs[p], rbase, 0, lane, acc);
            int n0r = base + rbase + (lane >> 2);
#pragma unroll
            for (int nt = 0; nt < 8; nt++) {
                int col = nt * 8 + 2 * (lane & 3);
                if (n0r < NN)
                    *(float2*)&outs[p][(size_t)n0r * 64 + col] =
                        make_float2(acc[nt][0], acc[nt][1]);
                if (n0r + 8 < NN)
                    *(float2*)&outs[p][(size_t)(n0r + 8) * 64 + col] =
                        make_float2(acc[nt][2], acc[nt][3]);
            }
        }
    }
}

// ============================================================================
// edge kernel (512 thr, 128-edge tiles, ldmatrix + fused gathers, 4 barriers)
// ============================================================================
__global__ void __launch_bounds__(512) edge_kernel(
    const float* __restrict__ pos,
    const int* __restrict__ src, const int* __restrict__ dst,
    const float* __restrict__ posw1, const float* __restrict__ posb1,
    const float* __restrict__ posw2, const float* __restrict__ posb2,
    const float* __restrict__ attw1, const float* __restrict__ attb1,
    const float* __restrict__ attw2, const float* __restrict__ attb2)
{
    extern __shared__ float sm[];
    float* sw1  = sm;                  // 192
    float* sb1  = sm + 192;            // 64
    float* sb2  = sm + 256;            // 64
    float* sab1 = sm + 320;            // 64
    float* sab2 = sm + 384;            // 64 -> 448
    float* wp2T = sm + 448;            // 4352
    float* wa1T = sm + 4800;           // 4352
    float* wa2T = sm + 9152;           // 4352 -> 13504
    float* bufA = sm + 13504;          // 8704
    float* bufB = sm + 22208;          // 8704
    float* bufD = sm + 30912;          // 8704 -> 39616
    int*   sidx = (int*)(sm + 39616);  // 128
    int*   didx = (int*)(sm + 39744);  // 128 -> total 39872 floats (155.75 KB)

    int t = threadIdx.x;
    for (int i = t; i < 4096; i += 512) {
        int k = i >> 6, n = i & 63;
        wp2T[n * RS + k] = to_tf32(posw2[i]);
        wa1T[n * RS + k] = to_tf32(attw1[i]);
        wa2T[n * RS + k] = to_tf32(attw2[i]);
    }
    if (t < 192) sw1[t] = posw1[t];
    if (t < 64) { sb1[t] = posb1[t]; sb2[t] = posb2[t];
                  sab1[t] = attb1[t]; sab2[t] = attb2[t]; }
    __syncthreads();

    int w = t >> 5, lane = t & 31;
    int rbase = (w & 7) * 16;        // 8 M-groups of 16 edges
    int n0base = (w >> 3) * 32;      // 2 N-halves
    int cg = t & 3, c0 = cg * 16;    // row-layout mapping
    int el = t >> 2;                 // local edge 0..127
    const int ntiles = EE / 128;     // 12500

    for (int tile = blockIdx.x; tile < ntiles; tile += gridDim.x) {
        // ---- phase 1: indices + pos delta + layer 1 (K=3), all per-thread ----
        int e = tile * 128 + el;
        int sE = __ldg(src + e), dE = __ldg(dst + e);
        if (cg == 0) { sidx[el] = sE; didx[el] = dE; }
        {
            float p0 = __ldg(pos + dE * 3 + 0) - __ldg(pos + sE * 3 + 0);
            float p1 = __ldg(pos + dE * 3 + 1) - __ldg(pos + sE * 3 + 1);
            float p2 = __ldg(pos + dE * 3 + 2) - __ldg(pos + sE * 3 + 2);
#pragma unroll
            for (int j = 0; j < 4; j++) {
                int col = c0 + 4 * j;
                float4 b  = *(float4*)&sb1[col];
                float4 w0 = *(float4*)&sw1[col];
                float4 w1r = *(float4*)&sw1[64 + col];
                float4 w2r = *(float4*)&sw1[128 + col];
                float4 a;
                a.x = fmaxf(fmaf(p2, w2r.x, fmaf(p1, w1r.x, fmaf(p0, w0.x, b.x))), 0.f);
                a.y = fmaxf(fmaf(p2, w2r.y, fmaf(p1, w1r.y, fmaf(p0, w0.y, b.y))), 0.f);
                a.z = fmaxf(fmaf(p2, w2r.z, fmaf(p1, w1r.z, fmaf(p0, w0.z, b.z))), 0.f);
                a.w = fmaxf(fmaf(p2, w2r.w, fmaf(p1, w1r.w, fmaf(p0, w0.w, b.w))), 0.f);
                a.x = to_tf32(a.x); a.y = to_tf32(a.y);
                a.z = to_tf32(a.z); a.w = to_tf32(a.w);
                *(float4*)&bufA[(size_t)el * RS + col] = a;
            }
        }
        __syncthreads();

        // ---- phase 2: prefetch adst/asrc (frag layout), layer-2 MMA, fused store ----
        {
            int er0 = rbase + (lane >> 2);
            int d0 = didx[er0], d1 = didx[er0 + 8];
            int s0 = sidx[er0], s1 = sidx[er0 + 8];
            float2 ad0[4], ad1[4], as0[4], as1[4];
#pragma unroll
            for (int nt = 0; nt < 4; nt++) {
                int col = n0base + nt * 8 + 2 * (lane & 3);
                ad0[nt] = *(const float2*)&g_adst[(size_t)d0 * 64 + col];
                ad1[nt] = *(const float2*)&g_adst[(size_t)d1 * 64 + col];
                as0[nt] = *(const float2*)&g_asrc[(size_t)s0 * 64 + col];
                as1[nt] = *(const float2*)&g_asrc[(size_t)s1 * 64 + col];
            }
            float acc[4][4];
            zero_acc<4>(acc);
            gemm_ldsm<4>(bufA, wp2T, rbase, n0base, lane, acc);
#pragma unroll
            for (int nt = 0; nt < 4; nt++) {
                int col = n0base + nt * 8 + 2 * (lane & 3);
                float2 b = *(const float2*)&sb2[col];
                float D00 = fmaxf(acc[nt][0] + b.x, 0.f);
                float D01 = fmaxf(acc[nt][1] + b.y, 0.f);
                float D10 = fmaxf(acc[nt][2] + b.x, 0.f);
                float D11 = fmaxf(acc[nt][3] + b.y, 0.f);
                *(float2*)&bufD[(size_t)er0 * RS + col] = make_float2(D00, D01);
                *(float2*)&bufD[(size_t)(er0 + 8) * RS + col] = make_float2(D10, D11);
                float t00 = to_tf32(ad0[nt].x - as0[nt].x + D00);
                float t01 = to_tf32(ad0[nt].y - as0[nt].y + D01);
                float t10 = to_tf32(ad1[nt].x - as1[nt].x + D10);
                float t11 = to_tf32(ad1[nt].y - as1[nt].y + D11);
                *(float2*)&bufB[(size_t)er0 * RS + col] = make_float2(t00, t01);
                *(float2*)&bufB[(size_t)(er0 + 8) * RS + col] = make_float2(t10, t11);
            }
        }
        __syncthreads();

        // ---- phase 3: h2 = relu(t@attW1+b1) -> bufA ----
        {
            float acc[4][4];
            zero_acc<4>(acc);
            gemm_ldsm<4>(bufB, wa1T, rbase, n0base, lane, acc);
            frag_store<4, 0>(bufA, sab1, rbase, n0base, lane, acc);
        }
        __syncthreads();

        // ---- phase 4: prefetch v (row layout), layer-4 MMA, ex -> bufB ----
        float4 vv[4];
        {
#pragma unroll
            for (int j = 0; j < 4; j++)
                vv[j] = *(const float4*)&g_v[(size_t)sE * 64 + c0 + 4 * j];
            float acc[4][4];
            zero_acc<4>(acc);
            gemm_ldsm<4>(bufA, wa2T, rbase, n0base, lane, acc);
            frag_store<4, 1>(bufB, sab2, rbase, n0base, lane, acc);
        }
        __syncthreads();

        // ---- scatter: num += ex*(v+delta); den += ex ----
        {
            float* nump = &g_num[(size_t)dE * 64 + c0];
            float* denp = &g_den[(size_t)dE * 64 + c0];
#pragma unroll
            for (int j = 0; j < 4; j++) {
                float4 ex = *(float4*)&bufB[(size_t)el * RS + c0 + 4 * j];
                float4 D  = *(float4*)&bufD[(size_t)el * RS + c0 + 4 * j];
                float4 V  = vv[j];
                float4 m;
                m.x = ex.x * (V.x + D.x); m.y = ex.y * (V.y + D.y);
                m.z = ex.z * (V.z + D.z); m.w = ex.w * (V.w + D.w);
                red_add4(nump + 4 * j, m);
                red_add4(denp + 4 * j, ex);
            }
        }
        // next tile's phase-1 sync orders scatter reads vs. phase-2 writes
    }
}

// ============================================================================
// final (256 thr): out = relu((num/den)@W_out + b_out)
// ============================================================================
__global__ void __launch_bounds__(256) final_kernel(
    const float* __restrict__ W_out, const float* __restrict__ b_out,
    float* __restrict__ out)
{
    extern __shared__ float sm[];
    float* WoT  = sm;              // 4352
    float* bo   = sm + 4352;       // 64
    float* bufA = sm + 4416;       // 8704 -> 13120 floats

    int t = threadIdx.x;
    for (int i = t; i < 4096; i += 256) {
        int k = i >> 6, n = i & 63;
        WoT[n * RS + k] = to_tf32(W_out[i]);
    }
    if (t < 64) bo[t] = b_out[t];
    __syncthreads();

    int w = t >> 5, lane = t & 31;
    int rbase = w * 16;
    int ntiles = (NN + 127) / 128;

    for (int tile = blockIdx.x; tile < ntiles; tile += gridDim.x) {
        int base = tile * 128;
        __syncthreads();
#pragma unroll
        for (int rr = 0; rr < 8; rr++) {
            int i = t + 256 * rr;
            int row = i >> 4, col = (i & 15) * 4;
            int n = base + row;
            float4 v = make_float4(0, 0, 0, 0);
            if (n < NN) {
                float4 nu = *(const float4*)&g_num[(size_t)n * 64 + col];
                float4 de = *(const float4*)&g_den[(size_t)n * 64 + col];
                v.x = to_tf32(nu.x / (de.x + 1e-16f));
                v.y = to_tf32(nu.y / (de.y + 1e-16f));
                v.z = to_tf32(nu.z / (de.z + 1e-16f));
                v.w = to_tf32(nu.w / (de.w + 1e-16f));
            }
            *(float4*)&bufA[(size_t)row * RS + col] = v;
        }
        __syncthreads();

        float acc[8][4];
        zero_acc<8>(acc);
        gemm_ldsm<8>(bufA, WoT, rbase, 0, lane, acc);

        int n0r = base + rbase + (lane >> 2);
#pragma unroll
        for (int nt = 0; nt < 8; nt++) {
            int col = nt * 8 + 2 * (lane & 3);
            float2 b = *(const float2*)&bo[col];
            if (n0r < NN)
                *(float2*)&out[(size_t)n0r * 64 + col] =
                    make_float2(fmaxf(acc[nt][0] + b.x, 0.f),
                                fmaxf(acc[nt][1] + b.y, 0.f));
            if (n0r + 8 < NN)
                *(float2*)&out[(size_t)(n0r + 8) * 64 + col] =
                    make_float2(fmaxf(acc[nt][2] + b.x, 0.f),
                                fmaxf(acc[nt][3] + b.y, 0.f));
        }
    }
}

// ---------------- launch ----------------
extern "C" void kernel_launch(void* const* d_in, const int* in_sizes, int n_in,
                              void* d_out, int out_size)
{
    const float* x      = (const float*)d_in[0];
    const float* pos    = (const float*)d_in[1];
    const int*   ei     = (const int*)d_in[2];
    const float* W_in   = (const float*)d_in[3];
    const float* b_in   = (const float*)d_in[4];
    const float* W_out  = (const float*)d_in[5];
    const float* b_out  = (const float*)d_in[6];
    const float* W_lin  = (const float*)d_in[7];
    const float* W_src  = (const float*)d_in[8];
    const float* W_dst  = (const float*)d_in[9];
    const float* posw1  = (const float*)d_in[10];
    const float* posb1  = (const float*)d_in[11];
    const float* posw2  = (const float*)d_in[12];
    const float* posb2  = (const float*)d_in[13];
    const float* attw1  = (const float*)d_in[14];
    const float* attb1  = (const float*)d_in[15];
    const float* attw2  = (const float*)d_in[16];
    const float* attb2  = (const float*)d_in[17];
    float* out = (float*)d_out;

    const int NP_SMEM = 34880 * 4;   // 136.25 KB
    const int EK_SMEM = 39872 * 4;   // 155.75 KB
    const int FN_SMEM = 13120 * 4;
    cudaFuncSetAttribute(node_prep, cudaFuncAttributeMaxDynamicSharedMemorySize, NP_SMEM);
    cudaFuncSetAttribute(edge_kernel, cudaFuncAttributeMaxDynamicSharedMemorySize, EK_SMEM);
    cudaFuncSetAttribute(final_kernel, cudaFuncAttributeMaxDynamicSharedMemorySize, FN_SMEM);

    zero_kernel<<<1024, 256>>>();
    node_prep<<<148, 256, NP_SMEM>>>(x, W_in, b_in, W_lin, W_src, W_dst);
    edge_kernel<<<148, 512, EK_SMEM>>>(pos, ei, ei + EE,
                                       posw1, posb1, posw2, posb2,
                                       attw1, attb1, attw2, attb2);
    final_kernel<<<444, 256, FN_SMEM>>>(W_out, b_out, out);
}

// round 6
// speedup vs baseline: 1.2903x; 1.1459x over previous
#include <cuda_runtime.h>
#include <cstdint>
#include <math.h>

#define NN 100000
#define EE 1600000
#define RS 68              // padded smem row stride (floats)

// ---------------- device scratch ----------------
__device__ float g_asrc[NN * 64];
__device__ float g_adst[NN * 64];
__device__ float g_v[NN * 64];
__device__ float g_num[NN * 64];
__device__ float g_den[NN * 64];

// ---------------- helpers ----------------
__device__ __forceinline__ void red_add4(float* p, float4 v) {
    asm volatile("red.global.add.v4.f32 [%0], {%1,%2,%3,%4};"
                 :: "l"(p), "f"(v.x), "f"(v.y), "f"(v.z), "f"(v.w) : "memory");
}
__device__ __forceinline__ float to_tf32(float x) {
    unsigned u;
    asm("cvt.rna.tf32.f32 %0, %1;" : "=r"(u) : "f"(x));
    return __uint_as_float(u);
}
__device__ __forceinline__ void mma_tf32(float c[4], unsigned a0, unsigned a1,
                                         unsigned a2, unsigned a3,
                                         unsigned b0, unsigned b1) {
    asm volatile(
        "mma.sync.aligned.m16n8k8.row.col.f32.tf32.tf32.f32 "
        "{%0,%1,%2,%3},{%4,%5,%6,%7},{%8,%9},{%0,%1,%2,%3};"
        : "+f"(c[0]), "+f"(c[1]), "+f"(c[2]), "+f"(c[3])
        : "r"(a0), "r"(a1), "r"(a2), "r"(a3), "r"(b0), "r"(b1));
}
__device__ __forceinline__ void ldsm4(unsigned addr, unsigned& r0, unsigned& r1,
                                      unsigned& r2, unsigned& r3) {
    asm volatile("ldmatrix.sync.aligned.m8n8.x4.shared.b16 {%0,%1,%2,%3}, [%4];"
                 : "=r"(r0), "=r"(r1), "=r"(r2), "=r"(r3) : "r"(addr));
}

// ---- ldmatrix GEMM. NT must be even. ----
template<int NT>
__device__ __forceinline__ void gemm_ldsm(const float* __restrict__ buf,
                                          const float* __restrict__ WT,
                                          int rbase, int n0base, int lane,
                                          float acc[NT][4]) {
    unsigned aA = (unsigned)__cvta_generic_to_shared(
        buf + (rbase + (lane & 15)) * RS + ((lane >> 4) << 2));
    unsigned bA = (unsigned)__cvta_generic_to_shared(
        WT + (n0base + (lane & 7) + ((lane & 16) >> 1)) * RS + ((lane & 8) ? 4 : 0));
#pragma unroll
    for (int k0 = 0; k0 < 64; k0 += 8) {
        unsigned a0, a1, a2, a3;
        ldsm4(aA + k0 * 4, a0, a1, a2, a3);
#pragma unroll
        for (int p = 0; p < NT / 2; p++) {
            unsigned b0, b1, b2, b3;
            ldsm4(bA + (unsigned)(p * 16 * RS + k0) * 4, b0, b1, b2, b3);
            mma_tf32(acc[2 * p],     a0, a1, a2, a3, b0, b1);
            mma_tf32(acc[2 * p + 1], a0, a1, a2, a3, b2, b3);
        }
    }
}

template<int NT>
__device__ __forceinline__ void zero_acc(float acc[NT][4]) {
#pragma unroll
    for (int nt = 0; nt < NT; nt++)
#pragma unroll
        for (int j = 0; j < 4; j++) acc[nt][j] = 0.f;
}

template<int NT, int MODE>   // MODE 0: tf32(relu(+b)); MODE 1: exp(relu(+b))
__device__ __forceinline__ void frag_store(float* __restrict__ bufOut,
                                           const float* __restrict__ bias,
                                           int rbase, int n0base, int lane,
                                           float acc[NT][4]) {
    int r0 = rbase + (lane >> 2);
#pragma unroll
    for (int nt = 0; nt < NT; nt++) {
        int col = n0base + nt * 8 + 2 * (lane & 3);
        float2 b = *(const float2*)&bias[col];
        float v00 = fmaxf(acc[nt][0] + b.x, 0.f);
        float v01 = fmaxf(acc[nt][1] + b.y, 0.f);
        float v10 = fmaxf(acc[nt][2] + b.x, 0.f);
        float v11 = fmaxf(acc[nt][3] + b.y, 0.f);
        if (MODE == 0) {
            v00 = to_tf32(v00); v01 = to_tf32(v01);
            v10 = to_tf32(v10); v11 = to_tf32(v11);
        } else {
            v00 = __expf(v00); v01 = __expf(v01);
            v10 = __expf(v10); v11 = __expf(v11);
        }
        *(float2*)&bufOut[(size_t)r0 * RS + col] = make_float2(v00, v01);
        *(float2*)&bufOut[(size_t)(r0 + 8) * RS + col] = make_float2(v10, v11);
    }
}

// ---------------- init ----------------
__global__ void zero_kernel() {
    int i = blockIdx.x * blockDim.x + threadIdx.x;
    int stride = gridDim.x * blockDim.x;
    float4 z = make_float4(0.f, 0.f, 0.f, 0.f);
    for (; i < NN * 64 / 4; i += stride) {
        ((float4*)g_num)[i] = z;
        ((float4*)g_den)[i] = z;
    }
}

// ============================================================================
// node_prep (256 thr, 128-node tiles)
// ============================================================================
__global__ void __launch_bounds__(256) node_prep(
    const float* __restrict__ x,
    const float* __restrict__ W_in, const float* __restrict__ b_in,
    const float* __restrict__ W_lin, const float* __restrict__ W_src,
    const float* __restrict__ W_dst)
{
    extern __shared__ float sm[];
    float* WinT = sm;              // 4352
    float* WsT  = sm + 4352;
    float* WdT  = sm + 8704;
    float* WlT  = sm + 13056;
    float* bin  = sm + 17408;      // 64
    float* bufA = sm + 17472;      // 8704
    float* bufB = sm + 26176;      // 8704 -> 34880 floats

    int t = threadIdx.x;
    for (int i = t; i < 4096; i += 256) {
        int k = i >> 6, n = i & 63;
        WinT[n * RS + k] = to_tf32(W_in[i]);
        WsT[n * RS + k]  = to_tf32(W_src[i]);
        WdT[n * RS + k]  = to_tf32(W_dst[i]);
        WlT[n * RS + k]  = to_tf32(W_lin[i]);
    }
    if (t < 64) bin[t] = b_in[t];
    __syncthreads();

    int w = t >> 5, lane = t & 31;
    int rbase = w * 16;
    int ntiles = (NN + 127) / 128;

    for (int tile = blockIdx.x; tile < ntiles; tile += gridDim.x) {
        int base = tile * 128;
        __syncthreads();
#pragma unroll
        for (int rr = 0; rr < 8; rr++) {
            int i = t + 256 * rr;
            int row = i >> 4, col = (i & 15) * 4;
            int n = base + row;
            float4 v = make_float4(0, 0, 0, 0);
            if (n < NN) {
                v = *(const float4*)&x[(size_t)n * 64 + col];
                v.x = to_tf32(v.x); v.y = to_tf32(v.y);
                v.z = to_tf32(v.z); v.w = to_tf32(v.w);
            }
            *(float4*)&bufA[(size_t)row * RS + col] = v;
        }
        __syncthreads();

        {
            float acc[8][4];
            zero_acc<8>(acc);
            gemm_ldsm<8>(bufA, WinT, rbase, 0, lane, acc);
            frag_store<8, 0>(bufB, bin, rbase, 0, lane, acc);
        }
        __syncthreads();

        const float* WTs[3] = {WsT, WdT, WlT};
        float* outs[3] = {g_asrc, g_adst, g_v};
#pragma unroll
        for (int p = 0; p < 3; p++) {
            float acc[8][4];
            zero_acc<8>(acc);
            gemm_ldsm<8>(bufB, WTs[p], rbase, 0, lane, acc);
            int n0r = base + rbase + (lane >> 2);
#pragma unroll
            for (int nt = 0; nt < 8; nt++) {
                int col = nt * 8 + 2 * (lane & 3);
                if (n0r < NN)
                    *(float2*)&outs[p][(size_t)n0r * 64 + col] =
                        make_float2(acc[nt][0], acc[nt][1]);
                if (n0r + 8 < NN)
                    *(float2*)&outs[p][(size_t)(n0r + 8) * 64 + col] =
                        make_float2(acc[nt][2], acc[nt][3]);
            }
        }
    }
}

// ============================================================================
// edge kernel: warp-autonomous 16-edge tiles, zero CTA barriers in main loop
// 256 thr (8 warps), 2 CTAs/SM
// ============================================================================
__global__ void __launch_bounds__(256, 2) edge_kernel(
    const float* __restrict__ pos,
    const int* __restrict__ src, const int* __restrict__ dst,
    const float* __restrict__ posw1, const float* __restrict__ posb1,
    const float* __restrict__ posw2, const float* __restrict__ posb2,
    const float* __restrict__ attw1, const float* __restrict__ attb1,
    const float* __restrict__ attw2, const float* __restrict__ attb2)
{
    extern __shared__ float sm[];
    float* sw1  = sm;              // 192
    float* sb1  = sm + 192;        // 64
    float* sb2  = sm + 256;        // 64
    float* sab1 = sm + 320;        // 64
    float* sab2 = sm + 384;        // 64 -> 448
    float* wp2T = sm + 448;        // 4352
    float* wa1T = sm + 4800;       // 4352
    float* wa2T = sm + 9152;       // 4352 -> 13504

    int t = threadIdx.x;
    int wid = t >> 5, lane = t & 31;
    float* bufA = sm + 13504 + wid * 1152;       // 16*RS = 1088 floats
    int*   sidx = (int*)(bufA + 1088);           // 16
    int*   didx = (int*)(bufA + 1104);           // 16  (+32 pad) -> total 22720 floats

    for (int i = t; i < 4096; i += 256) {
        int k = i >> 6, n = i & 63;
        wp2T[n * RS + k] = to_tf32(posw2[i]);
        wa1T[n * RS + k] = to_tf32(attw1[i]);
        wa2T[n * RS + k] = to_tf32(attw2[i]);
    }
    if (t < 192) sw1[t] = posw1[t];
    if (t < 64) { sb1[t] = posb1[t]; sb2[t] = posb2[t];
                  sab1[t] = attb1[t]; sab2[t] = attb2[t]; }
    __syncthreads();

    int el  = lane >> 1;             // row-layout: local edge 0..15
    int c0r = (lane & 1) * 32;       // row-layout: 32 channels per lane
    int er0 = lane >> 2;             // frag rows er0, er0+8
    int cfr = 2 * (lane & 3);        // frag col offset

    const int nwt = gridDim.x * 8;
    for (int wt = blockIdx.x * 8 + wid; wt < EE / 16; wt += nwt) {
        int ebase = wt * 16;
        __syncwarp();   // prior tile's smem reads done before rewriting
        if (lane < 16) {
            int e = ebase + lane;
            sidx[lane] = __ldg(src + e);
            didx[lane] = __ldg(dst + e);
        }
        __syncwarp();

        int sE = sidx[el], dE = didx[el];
        // ---- layer 1 (K=3): h1 -> bufA (tf32) ----
        {
            float p0 = __ldg(pos + dE * 3 + 0) - __ldg(pos + sE * 3 + 0);
            float p1 = __ldg(pos + dE * 3 + 1) - __ldg(pos + sE * 3 + 1);
            float p2 = __ldg(pos + dE * 3 + 2) - __ldg(pos + sE * 3 + 2);
#pragma unroll
            for (int j = 0; j < 8; j++) {
                int col = c0r + 4 * j;
                float4 b   = *(float4*)&sb1[col];
                float4 w0  = *(float4*)&sw1[col];
                float4 w1r = *(float4*)&sw1[64 + col];
                float4 w2r = *(float4*)&sw1[128 + col];
                float4 a;
                a.x = fmaxf(fmaf(p2, w2r.x, fmaf(p1, w1r.x, fmaf(p0, w0.x, b.x))), 0.f);
                a.y = fmaxf(fmaf(p2, w2r.y, fmaf(p1, w1r.y, fmaf(p0, w0.y, b.y))), 0.f);
                a.z = fmaxf(fmaf(p2, w2r.z, fmaf(p1, w1r.z, fmaf(p0, w0.z, b.z))), 0.f);
                a.w = fmaxf(fmaf(p2, w2r.w, fmaf(p1, w1r.w, fmaf(p0, w0.w, b.w))), 0.f);
                a.x = to_tf32(a.x); a.y = to_tf32(a.y);
                a.z = to_tf32(a.z); a.w = to_tf32(a.w);
                *(float4*)&bufA[(size_t)el * RS + col] = a;
            }
        }
        __syncwarp();

        // ---- gathers (frag layout) + layer-2 GEMM ----
        int d0 = didx[er0], d1 = didx[er0 + 8];
        int s0 = sidx[er0], s1 = sidx[er0 + 8];
        float2 ad0[8], ad1[8], as0[8], as1[8];
#pragma unroll
        for (int nt = 0; nt < 8; nt++) {
            int col = nt * 8 + cfr;
            ad0[nt] = *(const float2*)&g_adst[(size_t)d0 * 64 + col];
            ad1[nt] = *(const float2*)&g_adst[(size_t)d1 * 64 + col];
            as0[nt] = *(const float2*)&g_asrc[(size_t)s0 * 64 + col];
            as1[nt] = *(const float2*)&g_asrc[(size_t)s1 * 64 + col];
        }
        float accD[8][4];
        zero_acc<8>(accD);
        gemm_ldsm<8>(bufA, wp2T, 0, 0, lane, accD);
        __syncwarp();
        // epilogue: delta kept in accD; t -> bufA
#pragma unroll
        for (int nt = 0; nt < 8; nt++) {
            int col = nt * 8 + cfr;
            float2 b = *(const float2*)&sb2[col];
            accD[nt][0] = fmaxf(accD[nt][0] + b.x, 0.f);
            accD[nt][1] = fmaxf(accD[nt][1] + b.y, 0.f);
            accD[nt][2] = fmaxf(accD[nt][2] + b.x, 0.f);
            accD[nt][3] = fmaxf(accD[nt][3] + b.y, 0.f);
            float t00 = to_tf32(ad0[nt].x - as0[nt].x + accD[nt][0]);
            float t01 = to_tf32(ad0[nt].y - as0[nt].y + accD[nt][1]);
            float t10 = to_tf32(ad1[nt].x - as1[nt].x + accD[nt][2]);
            float t11 = to_tf32(ad1[nt].y - as1[nt].y + accD[nt][3]);
            *(float2*)&bufA[(size_t)er0 * RS + col] = make_float2(t00, t01);
            *(float2*)&bufA[(size_t)(er0 + 8) * RS + col] = make_float2(t10, t11);
        }
        __syncwarp();

        // ---- layer 3: h2 = relu(t@attW1+b1) -> bufA ----
        {
            float acc[8][4];
            zero_acc<8>(acc);
            gemm_ldsm<8>(bufA, wa1T, 0, 0, lane, acc);
            __syncwarp();
            frag_store<8, 0>(bufA, sab1, 0, 0, lane, acc);
        }
        __syncwarp();

        // ---- layer 4 + softmax-accumulate ----
        {
            float acc[8][4];
            zero_acc<8>(acc);
            gemm_ldsm<8>(bufA, wa2T, 0, 0, lane, acc);
            // v gather (frag layout)
            float2 v0[8], v1[8];
#pragma unroll
            for (int nt = 0; nt < 8; nt++) {
                int col = nt * 8 + cfr;
                v0[nt] = *(const float2*)&g_v[(size_t)s0 * 64 + col];
                v1[nt] = *(const float2*)&g_v[(size_t)s1 * 64 + col];
            }
            // ex = exp(relu(acc+b))
#pragma unroll
            for (int nt = 0; nt < 8; nt++) {
                int col = nt * 8 + cfr;
                float2 b = *(const float2*)&sab2[col];
                acc[nt][0] = __expf(fmaxf(acc[nt][0] + b.x, 0.f));
                acc[nt][1] = __expf(fmaxf(acc[nt][1] + b.y, 0.f));
                acc[nt][2] = __expf(fmaxf(acc[nt][2] + b.x, 0.f));
                acc[nt][3] = __expf(fmaxf(acc[nt][3] + b.y, 0.f));
            }
            __syncwarp();
            // ex -> bufA, scatter den
#pragma unroll
            for (int nt = 0; nt < 8; nt++) {
                int col = nt * 8 + cfr;
                *(float2*)&bufA[(size_t)er0 * RS + col] =
                    make_float2(acc[nt][0], acc[nt][1]);
                *(float2*)&bufA[(size_t)(er0 + 8) * RS + col] =
                    make_float2(acc[nt][2], acc[nt][3]);
            }
            __syncwarp();
            {
                float* denp = &g_den[(size_t)dE * 64 + c0r];
#pragma unroll
                for (int j = 0; j < 8; j++)
                    red_add4(denp + 4 * j, *(float4*)&bufA[(size_t)el * RS + c0r + 4 * j]);
            }
            __syncwarp();
            // m = ex*(v+delta) -> bufA, scatter num
#pragma unroll
            for (int nt = 0; nt < 8; nt++) {
                int col = nt * 8 + cfr;
                float m00 = acc[nt][0] * (v0[nt].x + accD[nt][0]);
                float m01 = acc[nt][1] * (v0[nt].y + accD[nt][1]);
                float m10 = acc[nt][2] * (v1[nt].x + accD[nt][2]);
                float m11 = acc[nt][3] * (v1[nt].y + accD[nt][3]);
                *(float2*)&bufA[(size_t)er0 * RS + col] = make_float2(m00, m01);
                *(float2*)&bufA[(size_t)(er0 + 8) * RS + col] = make_float2(m10, m11);
            }
            __syncwarp();
            {
                float* nump = &g_num[(size_t)dE * 64 + c0r];
#pragma unroll
                for (int j = 0; j < 8; j++)
                    red_add4(nump + 4 * j, *(float4*)&bufA[(size_t)el * RS + c0r + 4 * j]);
            }
        }
    }
}

// ============================================================================
// final (256 thr): out = relu((num/den)@W_out + b_out)
// ============================================================================
__global__ void __launch_bounds__(256) final_kernel(
    const float* __restrict__ W_out, const float* __restrict__ b_out,
    float* __restrict__ out)
{
    extern __shared__ float sm[];
    float* WoT  = sm;              // 4352
    float* bo   = sm + 4352;       // 64
    float* bufA = sm + 4416;       // 8704 -> 13120 floats

    int t = threadIdx.x;
    for (int i = t; i < 4096; i += 256) {
        int k = i >> 6, n = i & 63;
        WoT[n * RS + k] = to_tf32(W_out[i]);
    }
    if (t < 64) bo[t] = b_out[t];
    __syncthreads();

    int w = t >> 5, lane = t & 31;
    int rbase = w * 16;
    int ntiles = (NN + 127) / 128;

    for (int tile = blockIdx.x; tile < ntiles; tile += gridDim.x) {
        int base = tile * 128;
        __syncthreads();
#pragma unroll
        for (int rr = 0; rr < 8; rr++) {
            int i = t + 256 * rr;
            int row = i >> 4, col = (i & 15) * 4;
            int n = base + row;
            float4 v = make_float4(0, 0, 0, 0);
            if (n < NN) {
                float4 nu = *(const float4*)&g_num[(size_t)n * 64 + col];
                float4 de = *(const float4*)&g_den[(size_t)n * 64 + col];
                v.x = to_tf32(nu.x / (de.x + 1e-16f));
                v.y = to_tf32(nu.y / (de.y + 1e-16f));
                v.z = to_tf32(nu.z / (de.z + 1e-16f));
                v.w = to_tf32(nu.w / (de.w + 1e-16f));
            }
            *(float4*)&bufA[(size_t)row * RS + col] = v;
        }
        __syncthreads();

        float acc[8][4];
        zero_acc<8>(acc);
        gemm_ldsm<8>(bufA, WoT, rbase, 0, lane, acc);

        int n0r = base + rbase + (lane >> 2);
#pragma unroll
        for (int nt = 0; nt < 8; nt++) {
            int col = nt * 8 + 2 * (lane & 3);
            float2 b = *(const float2*)&bo[col];
            if (n0r < NN)
                *(float2*)&out[(size_t)n0r * 64 + col] =
                    make_float2(fmaxf(acc[nt][0] + b.x, 0.f),
                                fmaxf(acc[nt][1] + b.y, 0.f));
            if (n0r + 8 < NN)
                *(float2*)&out[(size_t)(n0r + 8) * 64 + col] =
                    make_float2(fmaxf(acc[nt][2] + b.x, 0.f),
                                fmaxf(acc[nt][3] + b.y, 0.f));
        }
    }
}

// ---------------- launch ----------------
extern "C" void kernel_launch(void* const* d_in, const int* in_sizes, int n_in,
                              void* d_out, int out_size)
{
    const float* x      = (const float*)d_in[0];
    const float* pos    = (const float*)d_in[1];
    const int*   ei     = (const int*)d_in[2];
    const float* W_in   = (const float*)d_in[3];
    const float* b_in   = (const float*)d_in[4];
    const float* W_out  = (const float*)d_in[5];
    const float* b_out  = (const float*)d_in[6];
    const float* W_lin  = (const float*)d_in[7];
    const float* W_src  = (const float*)d_in[8];
    const float* W_dst  = (const float*)d_in[9];
    const float* posw1  = (const float*)d_in[10];
    const float* posb1  = (const float*)d_in[11];
    const float* posw2  = (const float*)d_in[12];
    const float* posb2  = (const float*)d_in[13];
    const float* attw1  = (const float*)d_in[14];
    const float* attb1  = (const float*)d_in[15];
    const float* attw2  = (const float*)d_in[16];
    const float* attb2  = (const float*)d_in[17];
    float* out = (float*)d_out;

    const int NP_SMEM = 34880 * 4;   // 136.25 KB
    const int EK_SMEM = 22720 * 4;   // 88.75 KB -> 2 CTAs/SM
    const int FN_SMEM = 13120 * 4;
    cudaFuncSetAttribute(node_prep, cudaFuncAttributeMaxDynamicSharedMemorySize, NP_SMEM);
    cudaFuncSetAttribute(edge_kernel, cudaFuncAttributeMaxDynamicSharedMemorySize, EK_SMEM);
    cudaFuncSetAttribute(final_kernel, cudaFuncAttributeMaxDynamicSharedMemorySize, FN_SMEM);

    zero_kernel<<<1024, 256>>>();
    node_prep<<<148, 256, NP_SMEM>>>(x, W_in, b_in, W_lin, W_src, W_dst);
    edge_kernel<<<296, 256, EK_SMEM>>>(pos, ei, ei + EE,
                                       posw1, posb1, posw2, posb2,
                                       attw1, attb1, attw2, attb2);
    final_kernel<<<444, 256, FN_SMEM>>>(W_out, b_out, out);
}

// round 8
// speedup vs baseline: 1.6524x; 1.2806x over previous
#include <cuda_runtime.h>
#include <cstdint>
#include <math.h>

#define NN 100000
#define EE 1600000
#define RS 68              // weight smem row stride (floats)
#define RSX 132            // activation buffer row stride (floats): 128 data + 4 pad
#define SCAN_T 512
#define SCAN_B ((NN + SCAN_T - 1) / SCAN_T)   // 196

// ---------------- device scratch ----------------
__device__ float g_asrc[NN * 64];
__device__ float g_adst[NN * 64];
__device__ float g_v[NN * 64];
__device__ float g_num[NN * 64];
__device__ float g_den[NN * 64];
__device__ int   g_cnt[NN];
__device__ int   g_off[NN];
__device__ int   g_cur[NN];
__device__ int   g_bsum[SCAN_B];
__device__ int   g_ssrc[EE];
__device__ int   g_sdst[EE];

// ---------------- helpers ----------------
__device__ __forceinline__ void red_add4(float* p, float4 v) {
    asm volatile("red.global.add.v4.f32 [%0], {%1,%2,%3,%4};"
                 :: "l"(p), "f"(v.x), "f"(v.y), "f"(v.z), "f"(v.w) : "memory");
}
__device__ __forceinline__ float to_tf32(float x) {
    unsigned u;
    asm("cvt.rna.tf32.f32 %0, %1;" : "=r"(u) : "f"(x));
    return __uint_as_float(u);
}
__device__ __forceinline__ void mma_tf32(float c[4], unsigned a0, unsigned a1,
                                         unsigned a2, unsigned a3,
                                         unsigned b0, unsigned b1) {
    asm volatile(
        "mma.sync.aligned.m16n8k8.row.col.f32.tf32.tf32.f32 "
        "{%0,%1,%2,%3},{%4,%5,%6,%7},{%8,%9},{%0,%1,%2,%3};"
        : "+f"(c[0]), "+f"(c[1]), "+f"(c[2]), "+f"(c[3])
        : "r"(a0), "r"(a1), "r"(a2), "r"(a3), "r"(b0), "r"(b1));
}
__device__ __forceinline__ void ldsm4(unsigned addr, unsigned& r0, unsigned& r1,
                                      unsigned& r2, unsigned& r3) {
    asm volatile("ldmatrix.sync.aligned.m8n8.x4.shared.b16 {%0,%1,%2,%3}, [%4];"
                 : "=r"(r0), "=r"(r1), "=r"(r2), "=r"(r3) : "r"(addr));
}

// ---- ldmatrix GEMM. NT even. SA = A-buffer row stride; weights use RS. ----
template<int NT, int SA>
__device__ __forceinline__ void gemm_ldsm(const float* __restrict__ buf,
                                          const float* __restrict__ WT,
                                          int rbase, int n0base, int lane,
                                          float acc[NT][4]) {
    unsigned aA = (unsigned)__cvta_generic_to_shared(
        buf + (rbase + (lane & 15)) * SA + ((lane >> 4) << 2));
    unsigned bA = (unsigned)__cvta_generic_to_shared(
        WT + (n0base + (lane & 7) + ((lane & 16) >> 1)) * RS + ((lane & 8) ? 4 : 0));
#pragma unroll
    for (int k0 = 0; k0 < 64; k0 += 8) {
        unsigned a0, a1, a2, a3;
        ldsm4(aA + k0 * 4, a0, a1, a2, a3);
#pragma unroll
        for (int p = 0; p < NT / 2; p++) {
            unsigned b0, b1, b2, b3;
            ldsm4(bA + (unsigned)(p * 16 * RS + k0) * 4, b0, b1, b2, b3);
            mma_tf32(acc[2 * p],     a0, a1, a2, a3, b0, b1);
            mma_tf32(acc[2 * p + 1], a0, a1, a2, a3, b2, b3);
        }
    }
}

template<int NT>
__device__ __forceinline__ void zero_acc(float acc[NT][4]) {
#pragma unroll
    for (int nt = 0; nt < NT; nt++)
#pragma unroll
        for (int j = 0; j < 4; j++) acc[nt][j] = 0.f;
}

template<int NT, int MODE, int SD>   // MODE 0: tf32(relu(+b)); MODE 1: exp(relu(+b))
__device__ __forceinline__ void frag_store(float* __restrict__ bufOut,
                                           const float* __restrict__ bias,
                                           int rbase, int n0base, int lane,
                                           float acc[NT][4]) {
    int r0 = rbase + (lane >> 2);
#pragma unroll
    for (int nt = 0; nt < NT; nt++) {
        int col = n0base + nt * 8 + 2 * (lane & 3);
        float2 b = *(const float2*)&bias[col];
        float v00 = fmaxf(acc[nt][0] + b.x, 0.f);
        float v01 = fmaxf(acc[nt][1] + b.y, 0.f);
        float v10 = fmaxf(acc[nt][2] + b.x, 0.f);
        float v11 = fmaxf(acc[nt][3] + b.y, 0.f);
        if (MODE == 0) {
            v00 = to_tf32(v00); v01 = to_tf32(v01);
            v10 = to_tf32(v10); v11 = to_tf32(v11);
        } else {
            v00 = __expf(v00); v01 = __expf(v01);
            v10 = __expf(v10); v11 = __expf(v11);
        }
        *(float2*)&bufOut[(size_t)r0 * SD + col] = make_float2(v00, v01);
        *(float2*)&bufOut[(size_t)(r0 + 8) * SD + col] = make_float2(v10, v11);
    }
}

// ---------------- init + sort chain ----------------
__global__ void zero_kernel() {
    int i = blockIdx.x * blockDim.x + threadIdx.x;
    int stride = gridDim.x * blockDim.x;
    float4 z = make_float4(0.f, 0.f, 0.f, 0.f);
    for (int j = i; j < NN * 64 / 4; j += stride) {
        ((float4*)g_num)[j] = z;
        ((float4*)g_den)[j] = z;
    }
    for (int j = i; j < NN; j += stride) g_cnt[j] = 0;
}

__global__ void hist_kernel(const int* __restrict__ dst) {
    int i = blockIdx.x * blockDim.x + threadIdx.x;
    int stride = gridDim.x * blockDim.x;
    for (; i < EE; i += stride) atomicAdd(&g_cnt[dst[i]], 1);
}

__global__ void scan1_kernel() {
    __shared__ int s[SCAN_T];
    int tid = threadIdx.x;
    int i = blockIdx.x * SCAN_T + tid;
    int v = (i < NN) ? g_cnt[i] : 0;
    s[tid] = v;
    __syncthreads();
#pragma unroll
    for (int off = 1; off < SCAN_T; off <<= 1) {
        int t2 = (tid >= off) ? s[tid - off] : 0;
        __syncthreads();
        s[tid] += t2;
        __syncthreads();
    }
    if (i < NN) g_off[i] = s[tid] - v;   // local exclusive
    if (tid == SCAN_T - 1) g_bsum[blockIdx.x] = s[SCAN_T - 1];
}

__global__ void scan2_kernel() {   // 512-thread inclusive->exclusive scan of 196 sums
    __shared__ int s[SCAN_T];
    int tid = threadIdx.x;
    int v = (tid < SCAN_B) ? g_bsum[tid] : 0;
    s[tid] = v;
    __syncthreads();
#pragma unroll
    for (int off = 1; off < SCAN_T; off <<= 1) {
        int t2 = (tid >= off) ? s[tid - off] : 0;
        __syncthreads();
        s[tid] += t2;
        __syncthreads();
    }
    if (tid < SCAN_B) g_bsum[tid] = s[tid] - v;
}

__global__ void scan3_kernel() {
    int i = blockIdx.x * SCAN_T + threadIdx.x;
    if (i < NN) {
        int o = g_off[i] + g_bsum[blockIdx.x];
        g_off[i] = o;
        g_cur[i] = o;
    }
}

__global__ void scatter_kernel(const int* __restrict__ src,
                               const int* __restrict__ dst) {
    int i = blockIdx.x * blockDim.x + threadIdx.x;
    int stride = gridDim.x * blockDim.x;
    for (; i < EE; i += stride) {
        int d = dst[i];
        int p = atomicAdd(&g_cur[d], 1);
        g_ssrc[p] = src[i];
        g_sdst[p] = d;
    }
}

// ============================================================================
// node_prep (256 thr, 128-node tiles)
// ============================================================================
__global__ void __launch_bounds__(256) node_prep(
    const float* __restrict__ x,
    const float* __restrict__ W_in, const float* __restrict__ b_in,
    const float* __restrict__ W_lin, const float* __restrict__ W_src,
    const float* __restrict__ W_dst)
{
    extern __shared__ float sm[];
    float* WinT = sm;              // 4352
    float* WsT  = sm + 4352;
    float* WdT  = sm + 8704;
    float* WlT  = sm + 13056;
    float* bin  = sm + 17408;      // 64
    float* bufA = sm + 17472;      // 8704
    float* bufB = sm + 26176;      // 8704 -> 34880 floats

    int t = threadIdx.x;
    for (int i = t; i < 4096; i += 256) {
        int k = i >> 6, n = i & 63;
        WinT[n * RS + k] = to_tf32(W_in[i]);
        WsT[n * RS + k]  = to_tf32(W_src[i]);
        WdT[n * RS + k]  = to_tf32(W_dst[i]);
        WlT[n * RS + k]  = to_tf32(W_lin[i]);
    }
    if (t < 64) bin[t] = b_in[t];
    __syncthreads();

    int w = t >> 5, lane = t & 31;
    int rbase = w * 16;
    int ntiles = (NN + 127) / 128;

    for (int tile = blockIdx.x; tile < ntiles; tile += gridDim.x) {
        int base = tile * 128;
        __syncthreads();
#pragma unroll
        for (int rr = 0; rr < 8; rr++) {
            int i = t + 256 * rr;
            int row = i >> 4, col = (i & 15) * 4;
            int n = base + row;
            float4 v = make_float4(0, 0, 0, 0);
            if (n < NN) {
                v = *(const float4*)&x[(size_t)n * 64 + col];
                v.x = to_tf32(v.x); v.y = to_tf32(v.y);
                v.z = to_tf32(v.z); v.w = to_tf32(v.w);
            }
            *(float4*)&bufA[(size_t)row * RS + col] = v;
        }
        __syncthreads();

        {
            float acc[8][4];
            zero_acc<8>(acc);
            gemm_ldsm<8, RS>(bufA, WinT, rbase, 0, lane, acc);
            frag_store<8, 0, RS>(bufB, bin, rbase, 0, lane, acc);
        }
        __syncthreads();

        const float* WTs[3] = {WsT, WdT, WlT};
        float* outs[3] = {g_asrc, g_adst, g_v};
#pragma unroll
        for (int p = 0; p < 3; p++) {
            float acc[8][4];
            zero_acc<8>(acc);
            gemm_ldsm<8, RS>(bufB, WTs[p], rbase, 0, lane, acc);
            int n0r = base + rbase + (lane >> 2);
#pragma unroll
            for (int nt = 0; nt < 8; nt++) {
                int col = nt * 8 + 2 * (lane & 3);
                if (n0r < NN)
                    *(float2*)&outs[p][(size_t)n0r * 64 + col] =
                        make_float2(acc[nt][0], acc[nt][1]);
                if (n0r + 8 < NN)
                    *(float2*)&outs[p][(size_t)(n0r + 8) * 64 + col] =
                        make_float2(acc[nt][2], acc[nt][3]);
            }
        }
    }
}

// ============================================================================
// edge kernel: warp-autonomous 16-edge tiles over dst-sorted edges,
// run-aggregated atomic scatter. 512 thr (16 warps), 1 CTA/SM.
// ============================================================================
__global__ void __launch_bounds__(512, 1) edge_kernel(
    const float* __restrict__ pos,
    const float* __restrict__ posw1, const float* __restrict__ posb1,
    const float* __restrict__ posw2, const float* __restrict__ posb2,
    const float* __restrict__ attw1, const float* __restrict__ attb1,
    const float* __restrict__ attw2, const float* __restrict__ attb2)
{
    extern __shared__ float sm[];
    float* sw1  = sm;              // 192
    float* sb1  = sm + 192;        // 64
    float* sb2  = sm + 256;        // 64
    float* sab1 = sm + 320;        // 64
    float* sab2 = sm + 384;        // 64 -> 448
    float* wp2T = sm + 448;        // 4352
    float* wa1T = sm + 4800;       // 4352
    float* wa2T = sm + 9152;       // 4352 -> 13504

    int t = threadIdx.x;
    int wid = t >> 5, lane = t & 31;
    float* wbuf = sm + 13504 + wid * 2144;   // 16*RSX = 2112 floats
    int*   sidx = (int*)(wbuf + 2112);       // 16
    int*   didx = (int*)(wbuf + 2128);       // 16 -> total 47808 floats (186.75 KB)

    for (int i = t; i < 4096; i += 512) {
        int k = i >> 6, n = i & 63;
        wp2T[n * RS + k] = to_tf32(posw2[i]);
        wa1T[n * RS + k] = to_tf32(attw1[i]);
        wa2T[n * RS + k] = to_tf32(attw2[i]);
    }
    if (t < 192) sw1[t] = posw1[t];
    if (t < 64) { sb1[t] = posb1[t]; sb2[t] = posb2[t];
                  sab1[t] = attb1[t]; sab2[t] = attb2[t]; }
    __syncthreads();

    int el  = lane >> 1;             // row-layout: local edge 0..15
    int c0r = (lane & 1) * 32;       // row-layout: 32 channels per lane
    int er0 = lane >> 2;             // frag rows er0, er0+8
    int cfr = 2 * (lane & 3);        // frag col offset
    int part = (lane < 16) ? 4 * lane : 64 + 4 * (lane - 16);  // reduce slot

    const int nwt = gridDim.x * 16;
    for (int wt = blockIdx.x * 16 + wid; wt < EE / 16; wt += nwt) {
        int ebase = wt * 16;
        __syncwarp();   // prior tile's smem reads done before rewriting
        if (lane < 16) {
            sidx[lane] = g_ssrc[ebase + lane];
            didx[lane] = g_sdst[ebase + lane];
        }
        __syncwarp();

        int sE = sidx[el], dE = didx[el];
        // ---- layer 1 (K=3): h1 -> wbuf (tf32) ----
        {
            float p0 = __ldg(pos + dE * 3 + 0) - __ldg(pos + sE * 3 + 0);
            float p1 = __ldg(pos + dE * 3 + 1) - __ldg(pos + sE * 3 + 1);
            float p2 = __ldg(pos + dE * 3 + 2) - __ldg(pos + sE * 3 + 2);
#pragma unroll
            for (int j = 0; j < 8; j++) {
                int col = c0r + 4 * j;
                float4 b   = *(float4*)&sb1[col];
                float4 w0  = *(float4*)&sw1[col];
                float4 w1r = *(float4*)&sw1[64 + col];
                float4 w2r = *(float4*)&sw1[128 + col];
                float4 a;
                a.x = fmaxf(fmaf(p2, w2r.x, fmaf(p1, w1r.x, fmaf(p0, w0.x, b.x))), 0.f);
                a.y = fmaxf(fmaf(p2, w2r.y, fmaf(p1, w1r.y, fmaf(p0, w0.y, b.y))), 0.f);
                a.z = fmaxf(fmaf(p2, w2r.z, fmaf(p1, w1r.z, fmaf(p0, w0.z, b.z))), 0.f);
                a.w = fmaxf(fmaf(p2, w2r.w, fmaf(p1, w1r.w, fmaf(p0, w0.w, b.w))), 0.f);
                a.x = to_tf32(a.x); a.y = to_tf32(a.y);
                a.z = to_tf32(a.z); a.w = to_tf32(a.w);
                *(float4*)&wbuf[(size_t)el * RSX + col] = a;
            }
        }
        __syncwarp();

        // ---- layer-2 GEMM; gathers folded into epilogue (low reg pressure) ----
        int d0 = didx[er0], d1 = didx[er0 + 8];
        int s0 = sidx[er0], s1 = sidx[er0 + 8];
        float accD[8][4];
        zero_acc<8>(accD);
        gemm_ldsm<8, RSX>(wbuf, wp2T, 0, 0, lane, accD);
        __syncwarp();
#pragma unroll
        for (int nt = 0; nt < 8; nt++) {
            int col = nt * 8 + cfr;
            float2 ad0 = *(const float2*)&g_adst[(size_t)d0 * 64 + col];
            float2 ad1 = *(const float2*)&g_adst[(size_t)d1 * 64 + col];
            float2 as0 = *(const float2*)&g_asrc[(size_t)s0 * 64 + col];
            float2 as1 = *(const float2*)&g_asrc[(size_t)s1 * 64 + col];
            float2 b = *(const float2*)&sb2[col];
            accD[nt][0] = fmaxf(accD[nt][0] + b.x, 0.f);
            accD[nt][1] = fmaxf(accD[nt][1] + b.y, 0.f);
            accD[nt][2] = fmaxf(accD[nt][2] + b.x, 0.f);
            accD[nt][3] = fmaxf(accD[nt][3] + b.y, 0.f);
            float t00 = to_tf32(ad0.x - as0.x + accD[nt][0]);
            float t01 = to_tf32(ad0.y - as0.y + accD[nt][1]);
            float t10 = to_tf32(ad1.x - as1.x + accD[nt][2]);
            float t11 = to_tf32(ad1.y - as1.y + accD[nt][3]);
            *(float2*)&wbuf[(size_t)er0 * RSX + col] = make_float2(t00, t01);
            *(float2*)&wbuf[(size_t)(er0 + 8) * RSX + col] = make_float2(t10, t11);
        }
        __syncwarp();

        // ---- layer 3: h2 = relu(t@attW1+b1) -> wbuf ----
        {
            float acc[8][4];
            zero_acc<8>(acc);
            gemm_ldsm<8, RSX>(wbuf, wa1T, 0, 0, lane, acc);
            __syncwarp();
            frag_store<8, 0, RSX>(wbuf, sab1, 0, 0, lane, acc);
        }
        __syncwarp();

        // ---- layer 4 + m/ex store (v gathered in epilogue) ----
        {
            float acc[8][4];
            zero_acc<8>(acc);
            gemm_ldsm<8, RSX>(wbuf, wa2T, 0, 0, lane, acc);
            __syncwarp();
#pragma unroll
            for (int nt = 0; nt < 8; nt++) {
                int col = nt * 8 + cfr;
                float2 v0 = *(const float2*)&g_v[(size_t)s0 * 64 + col];
                float2 v1 = *(const float2*)&g_v[(size_t)s1 * 64 + col];
                float2 b = *(const float2*)&sab2[col];
                float e00 = __expf(fmaxf(acc[nt][0] + b.x, 0.f));
                float e01 = __expf(fmaxf(acc[nt][1] + b.y, 0.f));
                float e10 = __expf(fmaxf(acc[nt][2] + b.x, 0.f));
                float e11 = __expf(fmaxf(acc[nt][3] + b.y, 0.f));
                // m -> cols [0,64)
                *(float2*)&wbuf[(size_t)er0 * RSX + col] =
                    make_float2(e00 * (v0.x + accD[nt][0]),
                                e01 * (v0.y + accD[nt][1]));
                *(float2*)&wbuf[(size_t)(er0 + 8) * RSX + col] =
                    make_float2(e10 * (v1.x + accD[nt][2]),
                                e11 * (v1.y + accD[nt][3]));
                // ex -> cols [64,128)
                *(float2*)&wbuf[(size_t)er0 * RSX + 64 + col] = make_float2(e00, e01);
                *(float2*)&wbuf[(size_t)(er0 + 8) * RSX + 64 + col] = make_float2(e10, e11);
            }
        }
        __syncwarp();

        // ---- run-aggregated scatter: one red.v4 warp-op per distinct dst ----
        {
            int i = 0;
            while (i < 16) {
                int d = didx[i];
                float4 a4 = make_float4(0.f, 0.f, 0.f, 0.f);
                int j = i;
                do {
                    float4 r = *(float4*)&wbuf[(size_t)j * RSX + part];
                    a4.x += r.x; a4.y += r.y; a4.z += r.z; a4.w += r.w;
                    j++;
                } while (j < 16 && didx[j] == d);
                float* tgt = (lane < 16)
                    ? &g_num[(size_t)d * 64 + 4 * lane]
                    : &g_den[(size_t)d * 64 + 4 * (lane - 16)];
                red_add4(tgt, a4);
                i = j;
            }
        }
    }
}

// ============================================================================
// final (256 thr): out = relu((num/den)@W_out + b_out)
// ============================================================================
__global__ void __launch_bounds__(256) final_kernel(
    const float* __restrict__ W_out, const float* __restrict__ b_out,
    float* __restrict__ out)
{
    extern __shared__ float sm[];
    float* WoT  = sm;              // 4352
    float* bo   = sm + 4352;       // 64
    float* bufA = sm + 4416;       // 8704 -> 13120 floats

    int t = threadIdx.x;
    for (int i = t; i < 4096; i += 256) {
        int k = i >> 6, n = i & 63;
        WoT[n * RS + k] = to_tf32(W_out[i]);
    }
    if (t < 64) bo[t] = b_out[t];
    __syncthreads();

    int w = t >> 5, lane = t & 31;
    int rbase = w * 16;
    int ntiles = (NN + 127) / 128;

    for (int tile = blockIdx.x; tile < ntiles; tile += gridDim.x) {
        int base = tile * 128;
        __syncthreads();
#pragma unroll
        for (int rr = 0; rr < 8; rr++) {
            int i = t + 256 * rr;
            int row = i >> 4, col = (i & 15) * 4;
            int n = base + row;
            float4 v = make_float4(0, 0, 0, 0);
            if (n < NN) {
                float4 nu = *(const float4*)&g_num[(size_t)n * 64 + col];
                float4 de = *(const float4*)&g_den[(size_t)n * 64 + col];
                v.x = to_tf32(nu.x / (de.x + 1e-16f));
                v.y = to_tf32(nu.y / (de.y + 1e-16f));
                v.z = to_tf32(nu.z / (de.z + 1e-16f));
                v.w = to_tf32(nu.w / (de.w + 1e-16f));
            }
            *(float4*)&bufA[(size_t)row * RS + col] = v;
        }
        __syncthreads();

        float acc[8][4];
        zero_acc<8>(acc);
        gemm_ldsm<8, RS>(bufA, WoT, rbase, 0, lane, acc);

        int n0r = base + rbase + (lane >> 2);
#pragma unroll
        for (int nt = 0; nt < 8; nt++) {
            int col = nt * 8 + 2 * (lane & 3);
            float2 b = *(const float2*)&bo[col];
            if (n0r < NN)
                *(float2*)&out[(size_t)n0r * 64 + col] =
                    make_float2(fmaxf(acc[nt][0] + b.x, 0.f),
                                fmaxf(acc[nt][1] + b.y, 0.f));
            if (n0r + 8 < NN)
                *(float2*)&out[(size_t)(n0r + 8) * 64 + col] =
                    make_float2(fmaxf(acc[nt][2] + b.x, 0.f),
                                fmaxf(acc[nt][3] + b.y, 0.f));
        }
    }
}

// ---------------- launch ----------------
extern "C" void kernel_launch(void* const* d_in, const int* in_sizes, int n_in,
                              void* d_out, int out_size)
{
    const float* x      = (const float*)d_in[0];
    const float* pos    = (const float*)d_in[1];
    const int*   ei     = (const int*)d_in[2];
    const float* W_in   = (const float*)d_in[3];
    const float* b_in   = (const float*)d_in[4];
    const float* W_out  = (const float*)d_in[5];
    const float* b_out  = (const float*)d_in[6];
    const float* W_lin  = (const float*)d_in[7];
    const float* W_src  = (const float*)d_in[8];
    const float* W_dst  = (const float*)d_in[9];
    const float* posw1  = (const float*)d_in[10];
    const float* posb1  = (const float*)d_in[11];
    const float* posw2  = (const float*)d_in[12];
    const float* posb2  = (const float*)d_in[13];
    const float* attw1  = (const float*)d_in[14];
    const float* attb1  = (const float*)d_in[15];
    const float* attw2  = (const float*)d_in[16];
    const float* attb2  = (const float*)d_in[17];
    float* out = (float*)d_out;

    const int NP_SMEM = 34880 * 4;   // 136.25 KB
    const int EK_SMEM = 47808 * 4;   // 186.75 KB -> 1 CTA (512 thr) / SM
    const int FN_SMEM = 13120 * 4;
    cudaFuncSetAttribute(node_prep, cudaFuncAttributeMaxDynamicSharedMemorySize, NP_SMEM);
    cudaFuncSetAttribute(edge_kernel, cudaFuncAttributeMaxDynamicSharedMemorySize, EK_SMEM);
    cudaFuncSetAttribute(final_kernel, cudaFuncAttributeMaxDynamicSharedMemorySize, FN_SMEM);

    const int* srcp = ei;
    const int* dstp = ei + EE;

    zero_kernel<<<1024, 256>>>();
    hist_kernel<<<1024, 256>>>(dstp);
    scan1_kernel<<<SCAN_B, SCAN_T>>>();
    scan2_kernel<<<1, SCAN_T>>>();
    scan3_kernel<<<SCAN_B, SCAN_T>>>();
    scatter_kernel<<<1024, 256>>>(srcp, dstp);
    node_prep<<<148, 256, NP_SMEM>>>(x, W_in, b_in, W_lin, W_src, W_dst);
    edge_kernel<<<148, 512, EK_SMEM>>>(pos,
                                       posw1, posb1, posw2, posb2,
                                       attw1, attb1, attw2, attb2);
    final_kernel<<<444, 256, FN_SMEM>>>(W_out, b_out, out);
}

// round 9
// speedup vs baseline: 2.0189x; 1.2218x over previous
#include <cuda_runtime.h>
#include <cuda_fp16.h>
#include <cstdint>
#include <math.h>

#define NN 100000
#define EE 1600000
#define RS 68              // fp32 weight smem row stride (floats) - node/final kernels
#define RSX 132            // fp32 m/ex buffer row stride (floats)
#define RSH 72             // fp16 row stride (halves) - edge kernel
#define SCAN_T 512
#define SCAN_B ((NN + SCAN_T - 1) / SCAN_T)   // 196

// ---------------- device scratch ----------------
__device__ float g_asrc[NN * 64];
__device__ float g_adst[NN * 64];
__device__ float g_v[NN * 64];
__device__ float g_num[NN * 64];
__device__ float g_den[NN * 64];
__device__ int   g_cnt[NN];
__device__ int   g_off[NN];
__device__ int   g_cur[NN];
__device__ int   g_bsum[SCAN_B];
__device__ int   g_ssrc[EE];
__device__ int   g_sdst[EE];

// ---------------- helpers ----------------
__device__ __forceinline__ void red_add4(float* p, float4 v) {
    asm volatile("red.global.add.v4.f32 [%0], {%1,%2,%3,%4};"
                 :: "l"(p), "f"(v.x), "f"(v.y), "f"(v.z), "f"(v.w) : "memory");
}
__device__ __forceinline__ float to_tf32(float x) {
    unsigned u;
    asm("cvt.rna.tf32.f32 %0, %1;" : "=r"(u) : "f"(x));
    return __uint_as_float(u);
}
__device__ __forceinline__ void mma_tf32(float c[4], unsigned a0, unsigned a1,
                                         unsigned a2, unsigned a3,
                                         unsigned b0, unsigned b1) {
    asm volatile(
        "mma.sync.aligned.m16n8k8.row.col.f32.tf32.tf32.f32 "
        "{%0,%1,%2,%3},{%4,%5,%6,%7},{%8,%9},{%0,%1,%2,%3};"
        : "+f"(c[0]), "+f"(c[1]), "+f"(c[2]), "+f"(c[3])
        : "r"(a0), "r"(a1), "r"(a2), "r"(a3), "r"(b0), "r"(b1));
}
__device__ __forceinline__ void mma_f16(float c[4], unsigned a0, unsigned a1,
                                        unsigned a2, unsigned a3,
                                        unsigned b0, unsigned b1) {
    asm volatile(
        "mma.sync.aligned.m16n8k16.row.col.f32.f16.f16.f32 "
        "{%0,%1,%2,%3},{%4,%5,%6,%7},{%8,%9},{%0,%1,%2,%3};"
        : "+f"(c[0]), "+f"(c[1]), "+f"(c[2]), "+f"(c[3])
        : "r"(a0), "r"(a1), "r"(a2), "r"(a3), "r"(b0), "r"(b1));
}
__device__ __forceinline__ void ldsm4(unsigned addr, unsigned& r0, unsigned& r1,
                                      unsigned& r2, unsigned& r3) {
    asm volatile("ldmatrix.sync.aligned.m8n8.x4.shared.b16 {%0,%1,%2,%3}, [%4];"
                 : "=r"(r0), "=r"(r1), "=r"(r2), "=r"(r3) : "r"(addr));
}

// ---- tf32 ldsm GEMM (node_prep / final) ----
template<int NT, int SA>
__device__ __forceinline__ void gemm_ldsm(const float* __restrict__ buf,
                                          const float* __restrict__ WT,
                                          int rbase, int n0base, int lane,
                                          float acc[NT][4]) {
    unsigned aA = (unsigned)__cvta_generic_to_shared(
        buf + (rbase + (lane & 15)) * SA + ((lane >> 4) << 2));
    unsigned bA = (unsigned)__cvta_generic_to_shared(
        WT + (n0base + (lane & 7) + ((lane & 16) >> 1)) * RS + ((lane & 8) ? 4 : 0));
#pragma unroll
    for (int k0 = 0; k0 < 64; k0 += 8) {
        unsigned a0, a1, a2, a3;
        ldsm4(aA + k0 * 4, a0, a1, a2, a3);
#pragma unroll
        for (int p = 0; p < NT / 2; p++) {
            unsigned b0, b1, b2, b3;
            ldsm4(bA + (unsigned)(p * 16 * RS + k0) * 4, b0, b1, b2, b3);
            mma_tf32(acc[2 * p],     a0, a1, a2, a3, b0, b1);
            mma_tf32(acc[2 * p + 1], a0, a1, a2, a3, b2, b3);
        }
    }
}

// ---- fp16 ldsm GEMM (edge kernel): A 16x64 halves @RSH, W 64x64 halves @RSH ----
__device__ __forceinline__ void gemm_h16(const __half* __restrict__ bufH,
                                         const __half* __restrict__ WH,
                                         int lane, float acc[8][4]) {
    unsigned aA = (unsigned)__cvta_generic_to_shared(bufH)
                + (unsigned)((lane & 15) * (RSH * 2) + ((lane >> 4) << 4));
    unsigned bA = (unsigned)__cvta_generic_to_shared(WH)
                + (unsigned)(((lane & 7) + ((lane & 16) >> 1)) * (RSH * 2)
                             + ((lane & 8) ? 16 : 0));
#pragma unroll
    for (int kb = 0; kb < 4; kb++) {
        unsigned a0, a1, a2, a3;
        ldsm4(aA + kb * 32, a0, a1, a2, a3);
#pragma unroll
        for (int p = 0; p < 4; p++) {
            unsigned b0, b1, b2, b3;
            ldsm4(bA + (unsigned)(p * 16 * RSH * 2 + kb * 32), b0, b1, b2, b3);
            mma_f16(acc[2 * p],     a0, a1, a2, a3, b0, b1);
            mma_f16(acc[2 * p + 1], a0, a1, a2, a3, b2, b3);
        }
    }
}

template<int NT>
__device__ __forceinline__ void zero_acc(float acc[NT][4]) {
#pragma unroll
    for (int nt = 0; nt < NT; nt++)
#pragma unroll
        for (int j = 0; j < 4; j++) acc[nt][j] = 0.f;
}

template<int NT, int MODE, int SD>
__device__ __forceinline__ void frag_store(float* __restrict__ bufOut,
                                           const float* __restrict__ bias,
                                           int rbase, int n0base, int lane,
                                           float acc[NT][4]) {
    int r0 = rbase + (lane >> 2);
#pragma unroll
    for (int nt = 0; nt < NT; nt++) {
        int col = n0base + nt * 8 + 2 * (lane & 3);
        float2 b = *(const float2*)&bias[col];
        float v00 = fmaxf(acc[nt][0] + b.x, 0.f);
        float v01 = fmaxf(acc[nt][1] + b.y, 0.f);
        float v10 = fmaxf(acc[nt][2] + b.x, 0.f);
        float v11 = fmaxf(acc[nt][3] + b.y, 0.f);
        if (MODE == 0) {
            v00 = to_tf32(v00); v01 = to_tf32(v01);
            v10 = to_tf32(v10); v11 = to_tf32(v11);
        } else {
            v00 = __expf(v00); v01 = __expf(v01);
            v10 = __expf(v10); v11 = __expf(v11);
        }
        *(float2*)&bufOut[(size_t)r0 * SD + col] = make_float2(v00, v01);
        *(float2*)&bufOut[(size_t)(r0 + 8) * SD + col] = make_float2(v10, v11);
    }
}

// ---------------- init + sort chain ----------------
__global__ void zero_kernel() {
    int i = blockIdx.x * blockDim.x + threadIdx.x;
    int stride = gridDim.x * blockDim.x;
    float4 z = make_float4(0.f, 0.f, 0.f, 0.f);
    for (int j = i; j < NN * 64 / 4; j += stride) {
        ((float4*)g_num)[j] = z;
        ((float4*)g_den)[j] = z;
    }
    for (int j = i; j < NN; j += stride) g_cnt[j] = 0;
}

__global__ void hist_kernel(const int* __restrict__ dst) {
    int i = blockIdx.x * blockDim.x + threadIdx.x;
    int stride = gridDim.x * blockDim.x;
    for (; i < EE; i += stride) atomicAdd(&g_cnt[dst[i]], 1);
}

__global__ void scan1_kernel() {
    __shared__ int s[SCAN_T];
    int tid = threadIdx.x;
    int i = blockIdx.x * SCAN_T + tid;
    int v = (i < NN) ? g_cnt[i] : 0;
    s[tid] = v;
    __syncthreads();
#pragma unroll
    for (int off = 1; off < SCAN_T; off <<= 1) {
        int t2 = (tid >= off) ? s[tid - off] : 0;
        __syncthreads();
        s[tid] += t2;
        __syncthreads();
    }
    if (i < NN) g_off[i] = s[tid] - v;
    if (tid == SCAN_T - 1) g_bsum[blockIdx.x] = s[SCAN_T - 1];
}

__global__ void scan2_kernel() {
    __shared__ int s[SCAN_T];
    int tid = threadIdx.x;
    int v = (tid < SCAN_B) ? g_bsum[tid] : 0;
    s[tid] = v;
    __syncthreads();
#pragma unroll
    for (int off = 1; off < SCAN_T; off <<= 1) {
        int t2 = (tid >= off) ? s[tid - off] : 0;
        __syncthreads();
        s[tid] += t2;
        __syncthreads();
    }
    if (tid < SCAN_B) g_bsum[tid] = s[tid] - v;
}

__global__ void scan3_kernel() {
    int i = blockIdx.x * SCAN_T + threadIdx.x;
    if (i < NN) {
        int o = g_off[i] + g_bsum[blockIdx.x];
        g_off[i] = o;
        g_cur[i] = o;
    }
}

__global__ void scatter_kernel(const int* __restrict__ src,
                               const int* __restrict__ dst) {
    int i = blockIdx.x * blockDim.x + threadIdx.x;
    int stride = gridDim.x * blockDim.x;
    for (; i < EE; i += stride) {
        int d = dst[i];
        int p = atomicAdd(&g_cur[d], 1);
        g_ssrc[p] = src[i];
        g_sdst[p] = d;
    }
}

// ============================================================================
// node_prep (256 thr, 128-node tiles) — tf32, unchanged
// ============================================================================
__global__ void __launch_bounds__(256) node_prep(
    const float* __restrict__ x,
    const float* __restrict__ W_in, const float* __restrict__ b_in,
    const float* __restrict__ W_lin, const float* __restrict__ W_src,
    const float* __restrict__ W_dst)
{
    extern __shared__ float sm[];
    float* WinT = sm;
    float* WsT  = sm + 4352;
    float* WdT  = sm + 8704;
    float* WlT  = sm + 13056;
    float* bin  = sm + 17408;
    float* bufA = sm + 17472;
    float* bufB = sm + 26176;      // -> 34880 floats

    int t = threadIdx.x;
    for (int i = t; i < 4096; i += 256) {
        int k = i >> 6, n = i & 63;
        WinT[n * RS + k] = to_tf32(W_in[i]);
        WsT[n * RS + k]  = to_tf32(W_src[i]);
        WdT[n * RS + k]  = to_tf32(W_dst[i]);
        WlT[n * RS + k]  = to_tf32(W_lin[i]);
    }
    if (t < 64) bin[t] = b_in[t];
    __syncthreads();

    int w = t >> 5, lane = t & 31;
    int rbase = w * 16;
    int ntiles = (NN + 127) / 128;

    for (int tile = blockIdx.x; tile < ntiles; tile += gridDim.x) {
        int base = tile * 128;
        __syncthreads();
#pragma unroll
        for (int rr = 0; rr < 8; rr++) {
            int i = t + 256 * rr;
            int row = i >> 4, col = (i & 15) * 4;
            int n = base + row;
            float4 v = make_float4(0, 0, 0, 0);
            if (n < NN) {
                v = *(const float4*)&x[(size_t)n * 64 + col];
                v.x = to_tf32(v.x); v.y = to_tf32(v.y);
                v.z = to_tf32(v.z); v.w = to_tf32(v.w);
            }
            *(float4*)&bufA[(size_t)row * RS + col] = v;
        }
        __syncthreads();

        {
            float acc[8][4];
            zero_acc<8>(acc);
            gemm_ldsm<8, RS>(bufA, WinT, rbase, 0, lane, acc);
            frag_store<8, 0, RS>(bufB, bin, rbase, 0, lane, acc);
        }
        __syncthreads();

        const float* WTs[3] = {WsT, WdT, WlT};
        float* outs[3] = {g_asrc, g_adst, g_v};
#pragma unroll
        for (int p = 0; p < 3; p++) {
            float acc[8][4];
            zero_acc<8>(acc);
            gemm_ldsm<8, RS>(bufB, WTs[p], rbase, 0, lane, acc);
            int n0r = base + rbase + (lane >> 2);
#pragma unroll
            for (int nt = 0; nt < 8; nt++) {
                int col = nt * 8 + 2 * (lane & 3);
                if (n0r < NN)
                    *(float2*)&outs[p][(size_t)n0r * 64 + col] =
                        make_float2(acc[nt][0], acc[nt][1]);
                if (n0r + 8 < NN)
                    *(float2*)&outs[p][(size_t)(n0r + 8) * 64 + col] =
                        make_float2(acc[nt][2], acc[nt][3]);
            }
        }
    }
}

// ============================================================================
// edge kernel: warp-autonomous 16-edge tiles, dst-sorted, fp16 MMA GEMMs,
// run-aggregated scatter. 576 thr (18 warps), 1 CTA/SM.
// ============================================================================
__global__ void __launch_bounds__(576, 1) edge_kernel(
    const float* __restrict__ pos,
    const float* __restrict__ posw1, const float* __restrict__ posb1,
    const float* __restrict__ posw2, const float* __restrict__ posb2,
    const float* __restrict__ attw1, const float* __restrict__ attb1,
    const float* __restrict__ attw2, const float* __restrict__ attb2)
{
    extern __shared__ float sm[];
    float* sw1  = sm;              // 192
    float* sb1  = sm + 192;        // 64
    float* sb2  = sm + 256;        // 64
    float* sab1 = sm + 320;        // 64
    float* sab2 = sm + 384;        // 64 -> 448
    __half* WhBase = (__half*)(sm + 448);      // 3 x 64 x RSH halves = 13824 halves
    __half* wp2H = WhBase;
    __half* wa1H = WhBase + 4608;
    __half* wa2H = WhBase + 9216;              // halves end = 448 + 6912 floats

    int t = threadIdx.x;
    int wid = t >> 5, lane = t & 31;
    // per-warp: 2112 floats m/ex buf + 576 floats (=1152 halves) act buf + 32 ints
    float*  wbufF = sm + 7360 + wid * 2720;
    __half* wbufH = (__half*)(wbufF + 2112);
    int*    sidx  = (int*)(wbufF + 2688);      // 16
    int*    didx  = sidx + 16;                 // 16 -> total 7360 + 18*2720 = 56320 floats

    for (int i = t; i < 4096; i += 576) {
        int k = i >> 6, n = i & 63;
        wp2H[n * RSH + k] = __float2half_rn(posw2[i]);
        wa1H[n * RSH + k] = __float2half_rn(attw1[i]);
        wa2H[n * RSH + k] = __float2half_rn(attw2[i]);
    }
    if (t < 192) sw1[t] = posw1[t];
    if (t < 64) { sb1[t] = posb1[t]; sb2[t] = posb2[t];
                  sab1[t] = attb1[t]; sab2[t] = attb2[t]; }
    __syncthreads();

    int el  = lane >> 1;             // row-layout: local edge 0..15
    int c0r = (lane & 1) * 32;       // row-layout: 32 channels per lane
    int er0 = lane >> 2;             // frag rows er0, er0+8
    int cfr = 2 * (lane & 3);        // frag col offset
    int part = (lane < 16) ? 4 * lane : 64 + 4 * (lane - 16);  // reduce slot

    const int nwt = gridDim.x * 18;
    for (int wt = blockIdx.x * 18 + wid; wt < EE / 16; wt += nwt) {
        int ebase = wt * 16;
        __syncwarp();
        if (lane < 16) {
            sidx[lane] = g_ssrc[ebase + lane];
            didx[lane] = g_sdst[ebase + lane];
        }
        __syncwarp();

        int sE = sidx[el], dE = didx[el];
        // ---- layer 1 (K=3, scalar): h1 -> wbufH (fp16) ----
        {
            float p0 = __ldg(pos + dE * 3 + 0) - __ldg(pos + sE * 3 + 0);
            float p1 = __ldg(pos + dE * 3 + 1) - __ldg(pos + sE * 3 + 1);
            float p2 = __ldg(pos + dE * 3 + 2) - __ldg(pos + sE * 3 + 2);
#pragma unroll
            for (int j = 0; j < 8; j++) {
                int col = c0r + 4 * j;
                float4 b   = *(float4*)&sb1[col];
                float4 w0  = *(float4*)&sw1[col];
                float4 w1r = *(float4*)&sw1[64 + col];
                float4 w2r = *(float4*)&sw1[128 + col];
                float ax = fmaxf(fmaf(p2, w2r.x, fmaf(p1, w1r.x, fmaf(p0, w0.x, b.x))), 0.f);
                float ay = fmaxf(fmaf(p2, w2r.y, fmaf(p1, w1r.y, fmaf(p0, w0.y, b.y))), 0.f);
                float az = fmaxf(fmaf(p2, w2r.z, fmaf(p1, w1r.z, fmaf(p0, w0.z, b.z))), 0.f);
                float aw = fmaxf(fmaf(p2, w2r.w, fmaf(p1, w1r.w, fmaf(p0, w0.w, b.w))), 0.f);
                *(__half2*)&wbufH[el * RSH + col]     = __floats2half2_rn(ax, ay);
                *(__half2*)&wbufH[el * RSH + col + 2] = __floats2half2_rn(az, aw);
            }
        }
        __syncwarp();

        // ---- layer 2 (fp16 MMA): delta in accD; gathers in epilogue ----
        int d0 = didx[er0], d1 = didx[er0 + 8];
        int s0 = sidx[er0], s1 = sidx[er0 + 8];
        float accD[8][4];
        zero_acc<8>(accD);
        gemm_h16(wbufH, wp2H, lane, accD);
        __syncwarp();
#pragma unroll
        for (int nt = 0; nt < 8; nt++) {
            int col = nt * 8 + cfr;
            float2 ad0 = *(const float2*)&g_adst[(size_t)d0 * 64 + col];
            float2 ad1 = *(const float2*)&g_adst[(size_t)d1 * 64 + col];
            float2 as0 = *(const float2*)&g_asrc[(size_t)s0 * 64 + col];
            float2 as1 = *(const float2*)&g_asrc[(size_t)s1 * 64 + col];
            float2 b = *(const float2*)&sb2[col];
            accD[nt][0] = fmaxf(accD[nt][0] + b.x, 0.f);
            accD[nt][1] = fmaxf(accD[nt][1] + b.y, 0.f);
            accD[nt][2] = fmaxf(accD[nt][2] + b.x, 0.f);
            accD[nt][3] = fmaxf(accD[nt][3] + b.y, 0.f);
            *(__half2*)&wbufH[er0 * RSH + col] =
                __floats2half2_rn(ad0.x - as0.x + accD[nt][0],
                                  ad0.y - as0.y + accD[nt][1]);
            *(__half2*)&wbufH[(er0 + 8) * RSH + col] =
                __floats2half2_rn(ad1.x - as1.x + accD[nt][2],
                                  ad1.y - as1.y + accD[nt][3]);
        }
        __syncwarp();

        // ---- layer 3 (fp16 MMA): h2 = relu(t@attW1+b1) -> wbufH ----
        {
            float acc[8][4];
            zero_acc<8>(acc);
            gemm_h16(wbufH, wa1H, lane, acc);
            __syncwarp();
#pragma unroll
            for (int nt = 0; nt < 8; nt++) {
                int col = nt * 8 + cfr;
                float2 b = *(const float2*)&sab1[col];
                *(__half2*)&wbufH[er0 * RSH + col] =
                    __floats2half2_rn(fmaxf(acc[nt][0] + b.x, 0.f),
                                      fmaxf(acc[nt][1] + b.y, 0.f));
                *(__half2*)&wbufH[(er0 + 8) * RSH + col] =
                    __floats2half2_rn(fmaxf(acc[nt][2] + b.x, 0.f),
                                      fmaxf(acc[nt][3] + b.y, 0.f));
            }
        }
        __syncwarp();

        // ---- layer 4 (fp16 MMA) + m/ex store (fp32) ----
        {
            float acc[8][4];
            zero_acc<8>(acc);
            gemm_h16(wbufH, wa2H, lane, acc);
            __syncwarp();
#pragma unroll
            for (int nt = 0; nt < 8; nt++) {
                int col = nt * 8 + cfr;
                float2 v0 = *(const float2*)&g_v[(size_t)s0 * 64 + col];
                float2 v1 = *(const float2*)&g_v[(size_t)s1 * 64 + col];
                float2 b = *(const float2*)&sab2[col];
                float e00 = __expf(fmaxf(acc[nt][0] + b.x, 0.f));
                float e01 = __expf(fmaxf(acc[nt][1] + b.y, 0.f));
                float e10 = __expf(fmaxf(acc[nt][2] + b.x, 0.f));
                float e11 = __expf(fmaxf(acc[nt][3] + b.y, 0.f));
                *(float2*)&wbufF[(size_t)er0 * RSX + col] =
                    make_float2(e00 * (v0.x + accD[nt][0]),
                                e01 * (v0.y + accD[nt][1]));
                *(float2*)&wbufF[(size_t)(er0 + 8) * RSX + col] =
                    make_float2(e10 * (v1.x + accD[nt][2]),
                                e11 * (v1.y + accD[nt][3]));
                *(float2*)&wbufF[(size_t)er0 * RSX + 64 + col] = make_float2(e00, e01);
                *(float2*)&wbufF[(size_t)(er0 + 8) * RSX + 64 + col] = make_float2(e10, e11);
            }
        }
        __syncwarp();

        // ---- run-aggregated scatter: one red.v4 warp-op per distinct dst ----
        {
            int i = 0;
            while (i < 16) {
                int d = didx[i];
                float4 a4 = make_float4(0.f, 0.f, 0.f, 0.f);
                int j = i;
                do {
                    float4 r = *(float4*)&wbufF[(size_t)j * RSX + part];
                    a4.x += r.x; a4.y += r.y; a4.z += r.z; a4.w += r.w;
                    j++;
                } while (j < 16 && didx[j] == d);
                float* tgt = (lane < 16)
                    ? &g_num[(size_t)d * 64 + 4 * lane]
                    : &g_den[(size_t)d * 64 + 4 * (lane - 16)];
                red_add4(tgt, a4);
                i = j;
            }
        }
    }
}

// ============================================================================
// final (256 thr): out = relu((num/den)@W_out + b_out) — tf32, unchanged
// ============================================================================
__global__ void __launch_bounds__(256) final_kernel(
    const float* __restrict__ W_out, const float* __restrict__ b_out,
    float* __restrict__ out)
{
    extern __shared__ float sm[];
    float* WoT  = sm;
    float* bo   = sm + 4352;
    float* bufA = sm + 4416;       // -> 13120 floats

    int t = threadIdx.x;
    for (int i = t; i < 4096; i += 256) {
        int k = i >> 6, n = i & 63;
        WoT[n * RS + k] = to_tf32(W_out[i]);
    }
    if (t < 64) bo[t] = b_out[t];
    __syncthreads();

    int w = t >> 5, lane = t & 31;
    int rbase = w * 16;
    int ntiles = (NN + 127) / 128;

    for (int tile = blockIdx.x; tile < ntiles; tile += gridDim.x) {
        int base = tile * 128;
        __syncthreads();
#pragma unroll
        for (int rr = 0; rr < 8; rr++) {
            int i = t + 256 * rr;
            int row = i >> 4, col = (i & 15) * 4;
            int n = base + row;
            float4 v = make_float4(0, 0, 0, 0);
            if (n < NN) {
                float4 nu = *(const float4*)&g_num[(size_t)n * 64 + col];
                float4 de = *(const float4*)&g_den[(size_t)n * 64 + col];
                v.x = to_tf32(nu.x / (de.x + 1e-16f));
                v.y = to_tf32(nu.y / (de.y + 1e-16f));
                v.z = to_tf32(nu.z / (de.z + 1e-16f));
                v.w = to_tf32(nu.w / (de.w + 1e-16f));
            }
            *(float4*)&bufA[(size_t)row * RS + col] = v;
        }
        __syncthreads();

        float acc[8][4];
        zero_acc<8>(acc);
        gemm_ldsm<8, RS>(bufA, WoT, rbase, 0, lane, acc);

        int n0r = base + rbase + (lane >> 2);
#pragma unroll
        for (int nt = 0; nt < 8; nt++) {
            int col = nt * 8 + 2 * (lane & 3);
            float2 b = *(const float2*)&bo[col];
            if (n0r < NN)
                *(float2*)&out[(size_t)n0r * 64 + col] =
                    make_float2(fmaxf(acc[nt][0] + b.x, 0.f),
                                fmaxf(acc[nt][1] + b.y, 0.f));
            if (n0r + 8 < NN)
                *(float2*)&out[(size_t)(n0r + 8) * 64 + col] =
                    make_float2(fmaxf(acc[nt][2] + b.x, 0.f),
                                fmaxf(acc[nt][3] + b.y, 0.f));
        }
    }
}

// ---------------- launch ----------------
extern "C" void kernel_launch(void* const* d_in, const int* in_sizes, int n_in,
                              void* d_out, int out_size)
{
    const float* x      = (const float*)d_in[0];
    const float* pos    = (const float*)d_in[1];
    const int*   ei     = (const int*)d_in[2];
    const float* W_in   = (const float*)d_in[3];
    const float* b_in   = (const float*)d_in[4];
    const float* W_out  = (const float*)d_in[5];
    const float* b_out  = (const float*)d_in[6];
    const float* W_lin  = (const float*)d_in[7];
    const float* W_src  = (const float*)d_in[8];
    const float* W_dst  = (const float*)d_in[9];
    const float* posw1  = (const float*)d_in[10];
    const float* posb1  = (const float*)d_in[11];
    const float* posw2  = (const float*)d_in[12];
    const float* posb2  = (const float*)d_in[13];
    const float* attw1  = (const float*)d_in[14];
    const float* attb1  = (const float*)d_in[15];
    const float* attw2  = (const float*)d_in[16];
    const float* attb2  = (const float*)d_in[17];
    float* out = (float*)d_out;

    const int NP_SMEM = 34880 * 4;   // 136.25 KB
    const int EK_SMEM = 56320 * 4;   // 220 KB -> 1 CTA (576 thr) / SM
    const int FN_SMEM = 13120 * 4;
    cudaFuncSetAttribute(node_prep, cudaFuncAttributeMaxDynamicSharedMemorySize, NP_SMEM);
    cudaFuncSetAttribute(edge_kernel, cudaFuncAttributeMaxDynamicSharedMemorySize, EK_SMEM);
    cudaFuncSetAttribute(final_kernel, cudaFuncAttributeMaxDynamicSharedMemorySize, FN_SMEM);

    const int* srcp = ei;
    const int* dstp = ei + EE;

    zero_kernel<<<1024, 256>>>();
    hist_kernel<<<1024, 256>>>(dstp);
    scan1_kernel<<<SCAN_B, SCAN_T>>>();
    scan2_kernel<<<1, SCAN_T>>>();
    scan3_kernel<<<SCAN_B, SCAN_T>>>();
    scatter_kernel<<<1024, 256>>>(srcp, dstp);
    node_prep<<<148, 256, NP_SMEM>>>(x, W_in, b_in, W_lin, W_src, W_dst);
    edge_kernel<<<148, 576, EK_SMEM>>>(pos,
                                       posw1, posb1, posw2, posb2,
                                       attw1, attb1, attw2, attb2);
    final_kernel<<<444, 256, FN_SMEM>>>(W_out, b_out, out);
}

// round 12
// speedup vs baseline: 2.2303x; 1.1047x over previous
#include <cuda_runtime.h>
#include <cuda_fp16.h>
#include <cstdint>
#include <math.h>

#define NN 100000
#define EE 1600000
#define RS 68              // fp32 weight smem row stride (floats) - node/final kernels
#define RSH 72             // fp16 activation row stride (halves) - edge kernel
#define RSM 136            // fp16 m/ex buffer row stride (halves): 128 data + 8 pad
#define SCAN_T 512
#define SCAN_B ((NN + SCAN_T - 1) / SCAN_T)   // 196

// ---------------- device scratch ----------------
__device__ float g_asrc[NN * 64];
__device__ float g_adst[NN * 64];
__device__ float g_v[NN * 64];
__device__ float g_num[NN * 64];
__device__ float g_den[NN * 64];
__device__ int   g_cnt[NN];
__device__ int   g_off[NN];
__device__ int   g_cur[NN];
__device__ int   g_bsum[SCAN_B];
__device__ int   g_ssrc[EE];
__device__ int   g_sdst[EE];

// ---------------- helpers ----------------
__device__ __forceinline__ void red_add4(float* p, float4 v) {
    asm volatile("red.global.add.v4.f32 [%0], {%1,%2,%3,%4};"
                 :: "l"(p), "f"(v.x), "f"(v.y), "f"(v.z), "f"(v.w) : "memory");
}
__device__ __forceinline__ float to_tf32(float x) {
    unsigned u;
    asm("cvt.rna.tf32.f32 %0, %1;" : "=r"(u) : "f"(x));
    return __uint_as_float(u);
}
__device__ __forceinline__ void mma_tf32(float c[4], unsigned a0, unsigned a1,
                                         unsigned a2, unsigned a3,
                                         unsigned b0, unsigned b1) {
    asm volatile(
        "mma.sync.aligned.m16n8k8.row.col.f32.tf32.tf32.f32 "
        "{%0,%1,%2,%3},{%4,%5,%6,%7},{%8,%9},{%0,%1,%2,%3};"
        : "+f"(c[0]), "+f"(c[1]), "+f"(c[2]), "+f"(c[3])
        : "r"(a0), "r"(a1), "r"(a2), "r"(a3), "r"(b0), "r"(b1));
}
__device__ __forceinline__ void mma_f16(float c[4], unsigned a0, unsigned a1,
                                        unsigned a2, unsigned a3,
                                        unsigned b0, unsigned b1) {
    asm volatile(
        "mma.sync.aligned.m16n8k16.row.col.f32.f16.f16.f32 "
        "{%0,%1,%2,%3},{%4,%5,%6,%7},{%8,%9},{%0,%1,%2,%3};"
        : "+f"(c[0]), "+f"(c[1]), "+f"(c[2]), "+f"(c[3])
        : "r"(a0), "r"(a1), "r"(a2), "r"(a3), "r"(b0), "r"(b1));
}
__device__ __forceinline__ void ldsm4(unsigned addr, unsigned& r0, unsigned& r1,
                                      unsigned& r2, unsigned& r3) {
    asm volatile("ldmatrix.sync.aligned.m8n8.x4.shared.b16 {%0,%1,%2,%3}, [%4];"
                 : "=r"(r0), "=r"(r1), "=r"(r2), "=r"(r3) : "r"(addr));
}

// ---- tf32 ldsm GEMM (node_prep / final) ----
template<int NT, int SA>
__device__ __forceinline__ void gemm_ldsm(const float* __restrict__ buf,
                                          const float* __restrict__ WT,
                                          int rbase, int n0base, int lane,
                                          float acc[NT][4]) {
    unsigned aA = (unsigned)__cvta_generic_to_shared(
        buf + (rbase + (lane & 15)) * SA + ((lane >> 4) << 2));
    unsigned bA = (unsigned)__cvta_generic_to_shared(
        WT + (n0base + (lane & 7) + ((lane & 16) >> 1)) * RS + ((lane & 8) ? 4 : 0));
#pragma unroll
    for (int k0 = 0; k0 < 64; k0 += 8) {
        unsigned a0, a1, a2, a3;
        ldsm4(aA + k0 * 4, a0, a1, a2, a3);
#pragma unroll
        for (int p = 0; p < NT / 2; p++) {
            unsigned b0, b1, b2, b3;
            ldsm4(bA + (unsigned)(p * 16 * RS + k0) * 4, b0, b1, b2, b3);
            mma_tf32(acc[2 * p],     a0, a1, a2, a3, b0, b1);
            mma_tf32(acc[2 * p + 1], a0, a1, a2, a3, b2, b3);
        }
    }
}

// ---- fp16 ldsm GEMM (edge kernel): A 16x64 halves @RSH, W 64x64 halves @RSH ----
__device__ __forceinline__ void gemm_h16(const __half* __restrict__ bufH,
                                         const __half* __restrict__ WH,
                                         int lane, float acc[8][4]) {
    unsigned aA = (unsigned)__cvta_generic_to_shared(bufH)
                + (unsigned)((lane & 15) * (RSH * 2) + ((lane >> 4) << 4));
    unsigned bA = (unsigned)__cvta_generic_to_shared(WH)
                + (unsigned)(((lane & 7) + ((lane & 16) >> 1)) * (RSH * 2)
                             + ((lane & 8) ? 16 : 0));
#pragma unroll
    for (int kb = 0; kb < 4; kb++) {
        unsigned a0, a1, a2, a3;
        ldsm4(aA + kb * 32, a0, a1, a2, a3);
#pragma unroll
        for (int p = 0; p < 4; p++) {
            unsigned b0, b1, b2, b3;
            ldsm4(bA + (unsigned)(p * 16 * RSH * 2 + kb * 32), b0, b1, b2, b3);
            mma_f16(acc[2 * p],     a0, a1, a2, a3, b0, b1);
            mma_f16(acc[2 * p + 1], a0, a1, a2, a3, b2, b3);
        }
    }
}

template<int NT>
__device__ __forceinline__ void zero_acc(float acc[NT][4]) {
#pragma unroll
    for (int nt = 0; nt < NT; nt++)
#pragma unroll
        for (int j = 0; j < 4; j++) acc[nt][j] = 0.f;
}

template<int NT, int MODE, int SD>
__device__ __forceinline__ void frag_store(float* __restrict__ bufOut,
                                           const float* __restrict__ bias,
                                           int rbase, int n0base, int lane,
                                           float acc[NT][4]) {
    int r0 = rbase + (lane >> 2);
#pragma unroll
    for (int nt = 0; nt < NT; nt++) {
        int col = n0base + nt * 8 + 2 * (lane & 3);
        float2 b = *(const float2*)&bias[col];
        float v00 = fmaxf(acc[nt][0] + b.x, 0.f);
        float v01 = fmaxf(acc[nt][1] + b.y, 0.f);
        float v10 = fmaxf(acc[nt][2] + b.x, 0.f);
        float v11 = fmaxf(acc[nt][3] + b.y, 0.f);
        if (MODE == 0) {
            v00 = to_tf32(v00); v01 = to_tf32(v01);
            v10 = to_tf32(v10); v11 = to_tf32(v11);
        } else {
            v00 = __expf(v00); v01 = __expf(v01);
            v10 = __expf(v10); v11 = __expf(v11);
        }
        *(float2*)&bufOut[(size_t)r0 * SD + col] = make_float2(v00, v01);
        *(float2*)&bufOut[(size_t)(r0 + 8) * SD + col] = make_float2(v10, v11);
    }
}

// ---------------- init + sort chain ----------------
__global__ void zero_kernel() {
    int i = blockIdx.x * blockDim.x + threadIdx.x;
    int stride = gridDim.x * blockDim.x;
    float4 z = make_float4(0.f, 0.f, 0.f, 0.f);
    for (int j = i; j < NN * 64 / 4; j += stride) {
        ((float4*)g_num)[j] = z;
        ((float4*)g_den)[j] = z;
    }
    for (int j = i; j < NN; j += stride) g_cnt[j] = 0;
}

__global__ void hist_kernel(const int* __restrict__ dst) {
    int i = blockIdx.x * blockDim.x + threadIdx.x;
    int stride = gridDim.x * blockDim.x;
    for (; i < EE; i += stride) atomicAdd(&g_cnt[dst[i]], 1);
}

__global__ void scan1_kernel() {
    __shared__ int s[SCAN_T];
    int tid = threadIdx.x;
    int i = blockIdx.x * SCAN_T + tid;
    int v = (i < NN) ? g_cnt[i] : 0;
    s[tid] = v;
    __syncthreads();
#pragma unroll
    for (int off = 1; off < SCAN_T; off <<= 1) {
        int t2 = (tid >= off) ? s[tid - off] : 0;
        __syncthreads();
        s[tid] += t2;
        __syncthreads();
    }
    if (i < NN) g_off[i] = s[tid] - v;
    if (tid == SCAN_T - 1) g_bsum[blockIdx.x] = s[SCAN_T - 1];
}

__global__ void scan2_kernel() {
    __shared__ int s[SCAN_T];
    int tid = threadIdx.x;
    int v = (tid < SCAN_B) ? g_bsum[tid] : 0;
    s[tid] = v;
    __syncthreads();
#pragma unroll
    for (int off = 1; off < SCAN_T; off <<= 1) {
        int t2 = (tid >= off) ? s[tid - off] : 0;
        __syncthreads();
        s[tid] += t2;
        __syncthreads();
    }
    if (tid < SCAN_B) g_bsum[tid] = s[tid] - v;
}

__global__ void scan3_kernel() {
    int i = blockIdx.x * SCAN_T + threadIdx.x;
    if (i < NN) {
        int o = g_off[i] + g_bsum[blockIdx.x];
        g_off[i] = o;
        g_cur[i] = o;
    }
}

__global__ void scatter_kernel(const int* __restrict__ src,
                               const int* __restrict__ dst) {
    int i = blockIdx.x * blockDim.x + threadIdx.x;
    int stride = gridDim.x * blockDim.x;
    for (; i < EE; i += stride) {
        int d = dst[i];
        int p = atomicAdd(&g_cur[d], 1);
        g_ssrc[p] = src[i];
        g_sdst[p] = d;
    }
}

// ============================================================================
// node_prep (256 thr, 128-node tiles) — tf32, unchanged from R9
// ============================================================================
__global__ void __launch_bounds__(256) node_prep(
    const float* __restrict__ x,
    const float* __restrict__ W_in, const float* __restrict__ b_in,
    const float* __restrict__ W_lin, const float* __restrict__ W_src,
    const float* __restrict__ W_dst)
{
    extern __shared__ float sm[];
    float* WinT = sm;
    float* WsT  = sm + 4352;
    float* WdT  = sm + 8704;
    float* WlT  = sm + 13056;
    float* bin  = sm + 17408;
    float* bufA = sm + 17472;
    float* bufB = sm + 26176;      // -> 34880 floats

    int t = threadIdx.x;
    for (int i = t; i < 4096; i += 256) {
        int k = i >> 6, n = i & 63;
        WinT[n * RS + k] = to_tf32(W_in[i]);
        WsT[n * RS + k]  = to_tf32(W_src[i]);
        WdT[n * RS + k]  = to_tf32(W_dst[i]);
        WlT[n * RS + k]  = to_tf32(W_lin[i]);
    }
    if (t < 64) bin[t] = b_in[t];
    __syncthreads();

    int w = t >> 5, lane = t & 31;
    int rbase = w * 16;
    int ntiles = (NN + 127) / 128;

    for (int tile = blockIdx.x; tile < ntiles; tile += gridDim.x) {
        int base = tile * 128;
        __syncthreads();
#pragma unroll
        for (int rr = 0; rr < 8; rr++) {
            int i = t + 256 * rr;
            int row = i >> 4, col = (i & 15) * 4;
            int n = base + row;
            float4 v = make_float4(0, 0, 0, 0);
            if (n < NN) {
                v = *(const float4*)&x[(size_t)n * 64 + col];
                v.x = to_tf32(v.x); v.y = to_tf32(v.y);
                v.z = to_tf32(v.z); v.w = to_tf32(v.w);
            }
            *(float4*)&bufA[(size_t)row * RS + col] = v;
        }
        __syncthreads();

        {
            float acc[8][4];
            zero_acc<8>(acc);
            gemm_ldsm<8, RS>(bufA, WinT, rbase, 0, lane, acc);
            frag_store<8, 0, RS>(bufB, bin, rbase, 0, lane, acc);
        }
        __syncthreads();

        const float* WTs[3] = {WsT, WdT, WlT};
        float* outs[3] = {g_asrc, g_adst, g_v};
#pragma unroll
        for (int p = 0; p < 3; p++) {
            float acc[8][4];
            zero_acc<8>(acc);
            gemm_ldsm<8, RS>(bufB, WTs[p], rbase, 0, lane, acc);
            int n0r = base + rbase + (lane >> 2);
#pragma unroll
            for (int nt = 0; nt < 8; nt++) {
                int col = nt * 8 + 2 * (lane & 3);
                if (n0r < NN)
                    *(float2*)&outs[p][(size_t)n0r * 64 + col] =
                        make_float2(acc[nt][0], acc[nt][1]);
                if (n0r + 8 < NN)
                    *(float2*)&outs[p][(size_t)(n0r + 8) * 64 + col] =
                        make_float2(acc[nt][2], acc[nt][3]);
            }
        }
    }
}

// ============================================================================
// edge kernel: warp-autonomous 16-edge tiles, dst-sorted, fp16 MMA GEMMs,
// fp16 m/ex staging, run-aggregated scatter. 576 thr (18 warps), 1 CTA/SM.
// ============================================================================
__global__ void __launch_bounds__(576, 1) edge_kernel(
    const float* __restrict__ pos,
    const float* __restrict__ posw1, const float* __restrict__ posb1,
    const float* __restrict__ posw2, const float* __restrict__ posb2,
    const float* __restrict__ attw1, const float* __restrict__ attb1,
    const float* __restrict__ attw2, const float* __restrict__ attb2)
{
    extern __shared__ float sm[];
    float* sw1  = sm;              // 192
    float* sb1  = sm + 192;        // 64
    float* sb2  = sm + 256;        // 64
    float* sab1 = sm + 320;        // 64
    float* sab2 = sm + 384;        // 64 -> 448
    __half* WhBase = (__half*)(sm + 448);      // 3 x 64 x RSH halves = 13824 halves
    __half* wp2H = WhBase;
    __half* wa1H = WhBase + 4608;
    __half* wa2H = WhBase + 9216;              // ends at 448 + 6912 = 7360 floats

    int t = threadIdx.x;
    int wid = t >> 5, lane = t & 31;
    // per-warp block (1696 floats): m/ex fp16 buf (16*RSM=2176 halves = 1088 f),
    // act fp16 buf (16*RSH=1152 halves = 576 f), 32 ints idx (32 f)
    float*  wbase = sm + 7360 + wid * 1696;
    __half* wbufM = (__half*)wbase;
    __half* wbufH = (__half*)(wbase + 1088);
    int*    sidx  = (int*)(wbase + 1664);      // 16
    int*    didx  = sidx + 16;                 // 16 -> total 7360 + 18*1696 = 37888 floats

    for (int i = t; i < 4096; i += 576) {
        int k = i >> 6, n = i & 63;
        wp2H[n * RSH + k] = __float2half_rn(posw2[i]);
        wa1H[n * RSH + k] = __float2half_rn(attw1[i]);
        wa2H[n * RSH + k] = __float2half_rn(attw2[i]);
    }
    if (t < 192) sw1[t] = posw1[t];
    if (t < 64) { sb1[t] = posb1[t]; sb2[t] = posb2[t];
                  sab1[t] = attb1[t]; sab2[t] = attb2[t]; }
    __syncthreads();

    int el  = lane >> 1;             // row-layout: local edge 0..15
    int c0r = (lane & 1) * 32;       // row-layout: 32 channels per lane
    int er0 = lane >> 2;             // frag rows er0, er0+8
    int cfr = 2 * (lane & 3);        // frag col offset
    int part = (lane < 16) ? 4 * lane : 64 + 4 * (lane - 16);  // reduce slot (halves)

    const int nwt = gridDim.x * 18;
    for (int wt = blockIdx.x * 18 + wid; wt < EE / 16; wt += nwt) {
        int ebase = wt * 16;
        __syncwarp();
        if (lane < 16) {
            sidx[lane] = g_ssrc[ebase + lane];
            didx[lane] = g_sdst[ebase + lane];
        }
        __syncwarp();

        int sE = sidx[el], dE = didx[el];
        // ---- layer 1 (K=3, scalar): h1 -> wbufH (fp16) ----
        {
            float p0 = __ldg(pos + dE * 3 + 0) - __ldg(pos + sE * 3 + 0);
            float p1 = __ldg(pos + dE * 3 + 1) - __ldg(pos + sE * 3 + 1);
            float p2 = __ldg(pos + dE * 3 + 2) - __ldg(pos + sE * 3 + 2);
#pragma unroll
            for (int j = 0; j < 8; j++) {
                int col = c0r + 4 * j;
                float4 b   = *(float4*)&sb1[col];
                float4 w0  = *(float4*)&sw1[col];
                float4 w1r = *(float4*)&sw1[64 + col];
                float4 w2r = *(float4*)&sw1[128 + col];
                float ax = fmaxf(fmaf(p2, w2r.x, fmaf(p1, w1r.x, fmaf(p0, w0.x, b.x))), 0.f);
                float ay = fmaxf(fmaf(p2, w2r.y, fmaf(p1, w1r.y, fmaf(p0, w0.y, b.y))), 0.f);
                float az = fmaxf(fmaf(p2, w2r.z, fmaf(p1, w1r.z, fmaf(p0, w0.z, b.z))), 0.f);
                float aw = fmaxf(fmaf(p2, w2r.w, fmaf(p1, w1r.w, fmaf(p0, w0.w, b.w))), 0.f);
                *(__half2*)&wbufH[el * RSH + col]     = __floats2half2_rn(ax, ay);
                *(__half2*)&wbufH[el * RSH + col + 2] = __floats2half2_rn(az, aw);
            }
        }
        __syncwarp();

        // ---- layer 2 (fp16 MMA): delta in accD; gathers in epilogue ----
        int d0 = didx[er0], d1 = didx[er0 + 8];
        int s0 = sidx[er0], s1 = sidx[er0 + 8];
        float accD[8][4];
        zero_acc<8>(accD);
        gemm_h16(wbufH, wp2H, lane, accD);
        __syncwarp();
#pragma unroll
        for (int nt = 0; nt < 8; nt++) {
            int col = nt * 8 + cfr;
            float2 ad0 = *(const float2*)&g_adst[(size_t)d0 * 64 + col];
            float2 ad1 = *(const float2*)&g_adst[(size_t)d1 * 64 + col];
            float2 as0 = *(const float2*)&g_asrc[(size_t)s0 * 64 + col];
            float2 as1 = *(const float2*)&g_asrc[(size_t)s1 * 64 + col];
            float2 b = *(const float2*)&sb2[col];
            accD[nt][0] = fmaxf(accD[nt][0] + b.x, 0.f);
            accD[nt][1] = fmaxf(accD[nt][1] + b.y, 0.f);
            accD[nt][2] = fmaxf(accD[nt][2] + b.x, 0.f);
            accD[nt][3] = fmaxf(accD[nt][3] + b.y, 0.f);
            *(__half2*)&wbufH[er0 * RSH + col] =
                __floats2half2_rn(ad0.x - as0.x + accD[nt][0],
                                  ad0.y - as0.y + accD[nt][1]);
            *(__half2*)&wbufH[(er0 + 8) * RSH + col] =
                __floats2half2_rn(ad1.x - as1.x + accD[nt][2],
                                  ad1.y - as1.y + accD[nt][3]);
        }
        __syncwarp();

        // ---- layer 3 (fp16 MMA): h2 = relu(t@attW1+b1) -> wbufH ----
        {
            float acc[8][4];
            zero_acc<8>(acc);
            gemm_h16(wbufH, wa1H, lane, acc);
            __syncwarp();
#pragma unroll
            for (int nt = 0; nt < 8; nt++) {
                int col = nt * 8 + cfr;
                float2 b = *(const float2*)&sab1[col];
                *(__half2*)&wbufH[er0 * RSH + col] =
                    __floats2half2_rn(fmaxf(acc[nt][0] + b.x, 0.f),
                                      fmaxf(acc[nt][1] + b.y, 0.f));
                *(__half2*)&wbufH[(er0 + 8) * RSH + col] =
                    __floats2half2_rn(fmaxf(acc[nt][2] + b.x, 0.f),
                                      fmaxf(acc[nt][3] + b.y, 0.f));
            }
        }
        __syncwarp();

        // ---- layer 4 (fp16 MMA) + m/ex store (fp16) ----
        {
            float acc[8][4];
            zero_acc<8>(acc);
            gemm_h16(wbufH, wa2H, lane, acc);
            __syncwarp();
#pragma unroll
            for (int nt = 0; nt < 8; nt++) {
                int col = nt * 8 + cfr;
                float2 v0 = *(const float2*)&g_v[(size_t)s0 * 64 + col];
                float2 v1 = *(const float2*)&g_v[(size_t)s1 * 64 + col];
                float2 b = *(const float2*)&sab2[col];
                float e00 = __expf(fmaxf(acc[nt][0] + b.x, 0.f));
                float e01 = __expf(fmaxf(acc[nt][1] + b.y, 0.f));
                float e10 = __expf(fmaxf(acc[nt][2] + b.x, 0.f));
                float e11 = __expf(fmaxf(acc[nt][3] + b.y, 0.f));
                // m -> cols [0,64)
                *(__half2*)&wbufM[er0 * RSM + col] =
                    __floats2half2_rn(e00 * (v0.x + accD[nt][0]),
                                      e01 * (v0.y + accD[nt][1]));
                *(__half2*)&wbufM[(er0 + 8) * RSM + col] =
                    __floats2half2_rn(e10 * (v1.x + accD[nt][2]),
                                      e11 * (v1.y + accD[nt][3]));
                // ex -> cols [64,128)
                *(__half2*)&wbufM[er0 * RSM + 64 + col] = __floats2half2_rn(e00, e01);
                *(__half2*)&wbufM[(er0 + 8) * RSM + 64 + col] = __floats2half2_rn(e10, e11);
            }
        }
        __syncwarp();

        // ---- run-aggregated scatter: one red.v4 warp-op per distinct dst ----
        {
            int i = 0;
            while (i < 16) {
                int d = didx[i];
                float4 a4 = make_float4(0.f, 0.f, 0.f, 0.f);
                int j = i;
                do {
                    const __half2* p = (const __half2*)&wbufM[j * RSM + part];
                    float2 lo = __half22float2(p[0]);
                    float2 hi = __half22float2(p[1]);
                    a4.x += lo.x; a4.y += lo.y; a4.z += hi.x; a4.w += hi.y;
                    j++;
                } while (j < 16 && didx[j] == d);
                float* tgt = (lane < 16)
                    ? &g_num[(size_t)d * 64 + 4 * lane]
                    : &g_den[(size_t)d * 64 + 4 * (lane - 16)];
                red_add4(tgt, a4);
                i = j;
            }
        }
    }
}

// ============================================================================
// final (256 thr): out = relu((num/den)@W_out + b_out) — tf32, unchanged
// ============================================================================
__global__ void __launch_bounds__(256) final_kernel(
    const float* __restrict__ W_out, const float* __restrict__ b_out,
    float* __restrict__ out)
{
    extern __shared__ float sm[];
    float* WoT  = sm;
    float* bo   = sm + 4352;
    float* bufA = sm + 4416;       // -> 13120 floats

    int t = threadIdx.x;
    for (int i = t; i < 4096; i += 256) {
        int k = i >> 6, n = i & 63;
        WoT[n * RS + k] = to_tf32(W_out[i]);
    }
    if (t < 64) bo[t] = b_out[t];
    __syncthreads();

    int w = t >> 5, lane = t & 31;
    int rbase = w * 16;
    int ntiles = (NN + 127) / 128;

    for (int tile = blockIdx.x; tile < ntiles; tile += gridDim.x) {
        int base = tile * 128;
        __syncthreads();
#pragma unroll
        for (int rr = 0; rr < 8; rr++) {
            int i = t + 256 * rr;
            int row = i >> 4, col = (i & 15) * 4;
            int n = base + row;
            float4 v = make_float4(0, 0, 0, 0);
            if (n < NN) {
                float4 nu = *(const float4*)&g_num[(size_t)n * 64 + col];
                float4 de = *(const float4*)&g_den[(size_t)n * 64 + col];
                v.x = to_tf32(nu.x / (de.x + 1e-16f));
                v.y = to_tf32(nu.y / (de.y + 1e-16f));
                v.z = to_tf32(nu.z / (de.z + 1e-16f));
                v.w = to_tf32(nu.w / (de.w + 1e-16f));
            }
            *(float4*)&bufA[(size_t)row * RS + col] = v;
        }
        __syncthreads();

        float acc[8][4];
        zero_acc<8>(acc);
        gemm_ldsm<8, RS>(bufA, WoT, rbase, 0, lane, acc);

        int n0r = base + rbase + (lane >> 2);
#pragma unroll
        for (int nt = 0; nt < 8; nt++) {
            int col = nt * 8 + 2 * (lane & 3);
            float2 b = *(const float2*)&bo[col];
            if (n0r < NN)
                *(float2*)&out[(size_t)n0r * 64 + col] =
                    make_float2(fmaxf(acc[nt][0] + b.x, 0.f),
                                fmaxf(acc[nt][1] + b.y, 0.f));
            if (n0r + 8 < NN)
                *(float2*)&out[(size_t)(n0r + 8) * 64 + col] =
                    make_float2(fmaxf(acc[nt][2] + b.x, 0.f),
                                fmaxf(acc[nt][3] + b.y, 0.f));
        }
    }
}

// ---------------- launch ----------------
extern "C" void kernel_launch(void* const* d_in, const int* in_sizes, int n_in,
                              void* d_out, int out_size)
{
    const float* x      = (const float*)d_in[0];
    const float* pos    = (const float*)d_in[1];
    const int*   ei     = (const int*)d_in[2];
    const float* W_in   = (const float*)d_in[3];
    const float* b_in   = (const float*)d_in[4];
    const float* W_out  = (const float*)d_in[5];
    const float* b_out  = (const float*)d_in[6];
    const float* W_lin  = (const float*)d_in[7];
    const float* W_src  = (const float*)d_in[8];
    const float* W_dst  = (const float*)d_in[9];
    const float* posw1  = (const float*)d_in[10];
    const float* posb1  = (const float*)d_in[11];
    const float* posw2  = (const float*)d_in[12];
    const float* posb2  = (const float*)d_in[13];
    const float* attw1  = (const float*)d_in[14];
    const float* attb1  = (const float*)d_in[15];
    const float* attw2  = (const float*)d_in[16];
    const float* attb2  = (const float*)d_in[17];
    float* out = (float*)d_out;

    const int NP_SMEM = 34880 * 4;   // 136.25 KB
    const int EK_SMEM = 37888 * 4;   // 148 KB -> 1 CTA (576 thr) / SM
    const int FN_SMEM = 13120 * 4;
    cudaFuncSetAttribute(node_prep, cudaFuncAttributeMaxDynamicSharedMemorySize, NP_SMEM);
    cudaFuncSetAttribute(edge_kernel, cudaFuncAttributeMaxDynamicSharedMemorySize, EK_SMEM);
    cudaFuncSetAttribute(final_kernel, cudaFuncAttributeMaxDynamicSharedMemorySize, FN_SMEM);

    const int* srcp = ei;
    const int* dstp = ei + EE;

    zero_kernel<<<1024, 256>>>();
    hist_kernel<<<1024, 256>>>(dstp);
    scan1_kernel<<<SCAN_B, SCAN_T>>>();
    scan2_kernel<<<1, SCAN_T>>>();
    scan3_kernel<<<SCAN_B, SCAN_T>>>();
    scatter_kernel<<<1024, 256>>>(srcp, dstp);
    node_prep<<<148, 256, NP_SMEM>>>(x, W_in, b_in, W_lin, W_src, W_dst);
    edge_kernel<<<148, 576, EK_SMEM>>>(pos,
                                       posw1, posb1, posw2, posb2,
                                       attw1, attb1, attw2, attb2);
    final_kernel<<<444, 256, FN_SMEM>>>(W_out, b_out, out);
}

// round 13
// speedup vs baseline: 2.3109x; 1.0361x over previous
#include <cuda_runtime.h>
#include <cuda_fp16.h>
#include <cstdint>
#include <math.h>

#define NN 100000
#define EE 1600000
#define RS 68              // fp32 weight smem row stride (floats) - node/final kernels
#define RSH 72             // fp16 activation row stride (halves) - edge kernel
#define RSM 136            // fp16 m/ex buffer row stride (halves): 128 data + 8 pad
#define SCAN_T 512
#define SCAN_B ((NN + SCAN_T - 1) / SCAN_T)   // 196

// ---------------- device scratch ----------------
__device__ __half g_asrc[NN * 64];
__device__ __half g_adst[NN * 64];
__device__ __half g_v[NN * 64];
__device__ float  g_num[NN * 64];
__device__ float  g_den[NN * 64];
__device__ int    g_cnt[NN];
__device__ int    g_off[NN];
__device__ int    g_cur[NN];
__device__ int    g_bsum[SCAN_B];
__device__ int    g_ssrc[EE];
__device__ int    g_sdst[EE];

// ---------------- helpers ----------------
__device__ __forceinline__ void red_add4(float* p, float4 v) {
    asm volatile("red.global.add.v4.f32 [%0], {%1,%2,%3,%4};"
                 :: "l"(p), "f"(v.x), "f"(v.y), "f"(v.z), "f"(v.w) : "memory");
}
__device__ __forceinline__ float to_tf32(float x) {
    unsigned u;
    asm("cvt.rna.tf32.f32 %0, %1;" : "=r"(u) : "f"(x));
    return __uint_as_float(u);
}
__device__ __forceinline__ void mma_tf32(float c[4], unsigned a0, unsigned a1,
                                         unsigned a2, unsigned a3,
                                         unsigned b0, unsigned b1) {
    asm volatile(
        "mma.sync.aligned.m16n8k8.row.col.f32.tf32.tf32.f32 "
        "{%0,%1,%2,%3},{%4,%5,%6,%7},{%8,%9},{%0,%1,%2,%3};"
        : "+f"(c[0]), "+f"(c[1]), "+f"(c[2]), "+f"(c[3])
        : "r"(a0), "r"(a1), "r"(a2), "r"(a3), "r"(b0), "r"(b1));
}
__device__ __forceinline__ void mma_f16(float c[4], unsigned a0, unsigned a1,
                                        unsigned a2, unsigned a3,
                                        unsigned b0, unsigned b1) {
    asm volatile(
        "mma.sync.aligned.m16n8k16.row.col.f32.f16.f16.f32 "
        "{%0,%1,%2,%3},{%4,%5,%6,%7},{%8,%9},{%0,%1,%2,%3};"
        : "+f"(c[0]), "+f"(c[1]), "+f"(c[2]), "+f"(c[3])
        : "r"(a0), "r"(a1), "r"(a2), "r"(a3), "r"(b0), "r"(b1));
}
__device__ __forceinline__ void ldsm4(unsigned addr, unsigned& r0, unsigned& r1,
                                      unsigned& r2, unsigned& r3) {
    asm volatile("ldmatrix.sync.aligned.m8n8.x4.shared.b16 {%0,%1,%2,%3}, [%4];"
                 : "=r"(r0), "=r"(r1), "=r"(r2), "=r"(r3) : "r"(addr));
}

// ---- tf32 ldsm GEMM (node_prep / final) ----
template<int NT, int SA>
__device__ __forceinline__ void gemm_ldsm(const float* __restrict__ buf,
                                          const float* __restrict__ WT,
                                          int rbase, int n0base, int lane,
                                          float acc[NT][4]) {
    unsigned aA = (unsigned)__cvta_generic_to_shared(
        buf + (rbase + (lane & 15)) * SA + ((lane >> 4) << 2));
    unsigned bA = (unsigned)__cvta_generic_to_shared(
        WT + (n0base + (lane & 7) + ((lane & 16) >> 1)) * RS + ((lane & 8) ? 4 : 0));
#pragma unroll
    for (int k0 = 0; k0 < 64; k0 += 8) {
        unsigned a0, a1, a2, a3;
        ldsm4(aA + k0 * 4, a0, a1, a2, a3);
#pragma unroll
        for (int p = 0; p < NT / 2; p++) {
            unsigned b0, b1, b2, b3;
            ldsm4(bA + (unsigned)(p * 16 * RS + k0) * 4, b0, b1, b2, b3);
            mma_tf32(acc[2 * p],     a0, a1, a2, a3, b0, b1);
            mma_tf32(acc[2 * p + 1], a0, a1, a2, a3, b2, b3);
        }
    }
}

// ---- fp16 ldsm GEMM (edge kernel): A 16x64 halves @RSH, W 64x64 halves @RSH ----
__device__ __forceinline__ void gemm_h16(const __half* __restrict__ bufH,
                                         const __half* __restrict__ WH,
                                         int lane, float acc[8][4]) {
    unsigned aA = (unsigned)__cvta_generic_to_shared(bufH)
                + (unsigned)((lane & 15) * (RSH * 2) + ((lane >> 4) << 4));
    unsigned bA = (unsigned)__cvta_generic_to_shared(WH)
                + (unsigned)(((lane & 7) + ((lane & 16) >> 1)) * (RSH * 2)
                             + ((lane & 8) ? 16 : 0));
#pragma unroll
    for (int kb = 0; kb < 4; kb++) {
        unsigned a0, a1, a2, a3;
        ldsm4(aA + kb * 32, a0, a1, a2, a3);
#pragma unroll
        for (int p = 0; p < 4; p++) {
            unsigned b0, b1, b2, b3;
            ldsm4(bA + (unsigned)(p * 16 * RSH * 2 + kb * 32), b0, b1, b2, b3);
            mma_f16(acc[2 * p],     a0, a1, a2, a3, b0, b1);
            mma_f16(acc[2 * p + 1], a0, a1, a2, a3, b2, b3);
        }
    }
}

template<int NT>
__device__ __forceinline__ void zero_acc(float acc[NT][4]) {
#pragma unroll
    for (int nt = 0; nt < NT; nt++)
#pragma unroll
        for (int j = 0; j < 4; j++) acc[nt][j] = 0.f;
}

template<int NT, int MODE, int SD>
__device__ __forceinline__ void frag_store(float* __restrict__ bufOut,
                                           const float* __restrict__ bias,
                                           int rbase, int n0base, int lane,
                                           float acc[NT][4]) {
    int r0 = rbase + (lane >> 2);
#pragma unroll
    for (int nt = 0; nt < NT; nt++) {
        int col = n0base + nt * 8 + 2 * (lane & 3);
        float2 b = *(const float2*)&bias[col];
        float v00 = fmaxf(acc[nt][0] + b.x, 0.f);
        float v01 = fmaxf(acc[nt][1] + b.y, 0.f);
        float v10 = fmaxf(acc[nt][2] + b.x, 0.f);
        float v11 = fmaxf(acc[nt][3] + b.y, 0.f);
        if (MODE == 0) {
            v00 = to_tf32(v00); v01 = to_tf32(v01);
            v10 = to_tf32(v10); v11 = to_tf32(v11);
        } else {
            v00 = __expf(v00); v01 = __expf(v01);
            v10 = __expf(v10); v11 = __expf(v11);
        }
        *(float2*)&bufOut[(size_t)r0 * SD + col] = make_float2(v00, v01);
        *(float2*)&bufOut[(size_t)(r0 + 8) * SD + col] = make_float2(v10, v11);
    }
}

// ---------------- init + sort chain ----------------
__global__ void zero_kernel() {
    int i = blockIdx.x * blockDim.x + threadIdx.x;
    int stride = gridDim.x * blockDim.x;
    float4 z = make_float4(0.f, 0.f, 0.f, 0.f);
    for (int j = i; j < NN * 64 / 4; j += stride) {
        ((float4*)g_num)[j] = z;
        ((float4*)g_den)[j] = z;
    }
    for (int j = i; j < NN; j += stride) g_cnt[j] = 0;
}

__global__ void hist_kernel(const int* __restrict__ dst) {
    int i = blockIdx.x * blockDim.x + threadIdx.x;
    int stride = gridDim.x * blockDim.x;
    for (; i < EE; i += stride) atomicAdd(&g_cnt[dst[i]], 1);
}

__global__ void scan1_kernel() {
    __shared__ int s[SCAN_T];
    int tid = threadIdx.x;
    int i = blockIdx.x * SCAN_T + tid;
    int v = (i < NN) ? g_cnt[i] : 0;
    s[tid] = v;
    __syncthreads();
#pragma unroll
    for (int off = 1; off < SCAN_T; off <<= 1) {
        int t2 = (tid >= off) ? s[tid - off] : 0;
        __syncthreads();
        s[tid] += t2;
        __syncthreads();
    }
    if (i < NN) g_off[i] = s[tid] - v;
    if (tid == SCAN_T - 1) g_bsum[blockIdx.x] = s[SCAN_T - 1];
}

__global__ void scan2_kernel() {
    __shared__ int s[SCAN_T];
    int tid = threadIdx.x;
    int v = (tid < SCAN_B) ? g_bsum[tid] : 0;
    s[tid] = v;
    __syncthreads();
#pragma unroll
    for (int off = 1; off < SCAN_T; off <<= 1) {
        int t2 = (tid >= off) ? s[tid - off] : 0;
        __syncthreads();
        s[tid] += t2;
        __syncthreads();
    }
    if (tid < SCAN_B) g_bsum[tid] = s[tid] - v;
}

__global__ void scan3_kernel() {
    int i = blockIdx.x * SCAN_T + threadIdx.x;
    if (i < NN) {
        int o = g_off[i] + g_bsum[blockIdx.x];
        g_off[i] = o;
        g_cur[i] = o;
    }
}

__global__ void scatter_kernel(const int* __restrict__ src,
                               const int* __restrict__ dst) {
    int i = blockIdx.x * blockDim.x + threadIdx.x;
    int stride = gridDim.x * blockDim.x;
    for (; i < EE; i += stride) {
        int d = dst[i];
        int p = atomicAdd(&g_cur[d], 1);
        g_ssrc[p] = src[i];
        g_sdst[p] = d;
    }
}

// ============================================================================
// node_prep (256 thr, 128-node tiles) — tf32 GEMM, fp16 outputs
// ============================================================================
__global__ void __launch_bounds__(256) node_prep(
    const float* __restrict__ x,
    const float* __restrict__ W_in, const float* __restrict__ b_in,
    const float* __restrict__ W_lin, const float* __restrict__ W_src,
    const float* __restrict__ W_dst)
{
    extern __shared__ float sm[];
    float* WinT = sm;
    float* WsT  = sm + 4352;
    float* WdT  = sm + 8704;
    float* WlT  = sm + 13056;
    float* bin  = sm + 17408;
    float* bufA = sm + 17472;
    float* bufB = sm + 26176;      // -> 34880 floats

    int t = threadIdx.x;
    for (int i = t; i < 4096; i += 256) {
        int k = i >> 6, n = i & 63;
        WinT[n * RS + k] = to_tf32(W_in[i]);
        WsT[n * RS + k]  = to_tf32(W_src[i]);
        WdT[n * RS + k]  = to_tf32(W_dst[i]);
        WlT[n * RS + k]  = to_tf32(W_lin[i]);
    }
    if (t < 64) bin[t] = b_in[t];
    __syncthreads();

    int w = t >> 5, lane = t & 31;
    int rbase = w * 16;
    int ntiles = (NN + 127) / 128;

    for (int tile = blockIdx.x; tile < ntiles; tile += gridDim.x) {
        int base = tile * 128;
        __syncthreads();
#pragma unroll
        for (int rr = 0; rr < 8; rr++) {
            int i = t + 256 * rr;
            int row = i >> 4, col = (i & 15) * 4;
            int n = base + row;
            float4 v = make_float4(0, 0, 0, 0);
            if (n < NN) {
                v = *(const float4*)&x[(size_t)n * 64 + col];
                v.x = to_tf32(v.x); v.y = to_tf32(v.y);
                v.z = to_tf32(v.z); v.w = to_tf32(v.w);
            }
            *(float4*)&bufA[(size_t)row * RS + col] = v;
        }
        __syncthreads();

        {
            float acc[8][4];
            zero_acc<8>(acc);
            gemm_ldsm<8, RS>(bufA, WinT, rbase, 0, lane, acc);
            frag_store<8, 0, RS>(bufB, bin, rbase, 0, lane, acc);
        }
        __syncthreads();

        const float* WTs[3] = {WsT, WdT, WlT};
        __half* outs[3] = {g_asrc, g_adst, g_v};
#pragma unroll
        for (int p = 0; p < 3; p++) {
            float acc[8][4];
            zero_acc<8>(acc);
            gemm_ldsm<8, RS>(bufB, WTs[p], rbase, 0, lane, acc);
            int n0r = base + rbase + (lane >> 2);
#pragma unroll
            for (int nt = 0; nt < 8; nt++) {
                int col = nt * 8 + 2 * (lane & 3);
                if (n0r < NN)
                    *(__half2*)&outs[p][(size_t)n0r * 64 + col] =
                        __floats2half2_rn(acc[nt][0], acc[nt][1]);
                if (n0r + 8 < NN)
                    *(__half2*)&outs[p][(size_t)(n0r + 8) * 64 + col] =
                        __floats2half2_rn(acc[nt][2], acc[nt][3]);
            }
        }
    }
}

// ============================================================================
// edge kernel: warp-autonomous 16-edge tiles, dst-sorted, fp16 MMA GEMMs,
// fp16 node-array gathers, fp16 m/ex staging, run-aggregated scatter.
// 576 thr (18 warps), 1 CTA/SM.
// ============================================================================
__global__ void __launch_bounds__(576, 1) edge_kernel(
    const float* __restrict__ pos,
    const float* __restrict__ posw1, const float* __restrict__ posb1,
    const float* __restrict__ posw2, const float* __restrict__ posb2,
    const float* __restrict__ attw1, const float* __restrict__ attb1,
    const float* __restrict__ attw2, const float* __restrict__ attb2)
{
    extern __shared__ float sm[];
    float* sw1  = sm;              // 192
    float* sb1  = sm + 192;        // 64
    float* sb2  = sm + 256;        // 64
    float* sab1 = sm + 320;        // 64
    float* sab2 = sm + 384;        // 64 -> 448
    __half* WhBase = (__half*)(sm + 448);      // 3 x 64 x RSH halves
    __half* wp2H = WhBase;
    __half* wa1H = WhBase + 4608;
    __half* wa2H = WhBase + 9216;              // ends at 7360 floats

    int t = threadIdx.x;
    int wid = t >> 5, lane = t & 31;
    float*  wbase = sm + 7360 + wid * 1696;
    __half* wbufM = (__half*)wbase;            // 16*RSM = 2176 halves
    __half* wbufH = (__half*)(wbase + 1088);   // 16*RSH = 1152 halves
    int*    sidx  = (int*)(wbase + 1664);      // 16
    int*    didx  = sidx + 16;                 // 16 -> total 37888 floats

    for (int i = t; i < 4096; i += 576) {
        int k = i >> 6, n = i & 63;
        wp2H[n * RSH + k] = __float2half_rn(posw2[i]);
        wa1H[n * RSH + k] = __float2half_rn(attw1[i]);
        wa2H[n * RSH + k] = __float2half_rn(attw2[i]);
    }
    if (t < 192) sw1[t] = posw1[t];
    if (t < 64) { sb1[t] = posb1[t]; sb2[t] = posb2[t];
                  sab1[t] = attb1[t]; sab2[t] = attb2[t]; }
    __syncthreads();

    int el  = lane >> 1;             // row-layout: local edge 0..15
    int c0r = (lane & 1) * 32;       // row-layout: 32 channels per lane
    int er0 = lane >> 2;             // frag rows er0, er0+8
    int cfr = 2 * (lane & 3);        // frag col offset
    int part = (lane < 16) ? 4 * lane : 64 + 4 * (lane - 16);  // reduce slot

    const int nwt = gridDim.x * 18;
    for (int wt = blockIdx.x * 18 + wid; wt < EE / 16; wt += nwt) {
        int ebase = wt * 16;
        __syncwarp();
        if (lane < 16) {
            sidx[lane] = g_ssrc[ebase + lane];
            didx[lane] = g_sdst[ebase + lane];
        }
        __syncwarp();

        int sE = sidx[el], dE = didx[el];
        // ---- layer 1 (K=3, scalar): h1 -> wbufH (fp16) ----
        {
            float p0 = __ldg(pos + dE * 3 + 0) - __ldg(pos + sE * 3 + 0);
            float p1 = __ldg(pos + dE * 3 + 1) - __ldg(pos + sE * 3 + 1);
            float p2 = __ldg(pos + dE * 3 + 2) - __ldg(pos + sE * 3 + 2);
#pragma unroll
            for (int j = 0; j < 8; j++) {
                int col = c0r + 4 * j;
                float4 b   = *(float4*)&sb1[col];
                float4 w0  = *(float4*)&sw1[col];
                float4 w1r = *(float4*)&sw1[64 + col];
                float4 w2r = *(float4*)&sw1[128 + col];
                float ax = fmaxf(fmaf(p2, w2r.x, fmaf(p1, w1r.x, fmaf(p0, w0.x, b.x))), 0.f);
                float ay = fmaxf(fmaf(p2, w2r.y, fmaf(p1, w1r.y, fmaf(p0, w0.y, b.y))), 0.f);
                float az = fmaxf(fmaf(p2, w2r.z, fmaf(p1, w1r.z, fmaf(p0, w0.z, b.z))), 0.f);
                float aw = fmaxf(fmaf(p2, w2r.w, fmaf(p1, w1r.w, fmaf(p0, w0.w, b.w))), 0.f);
                *(__half2*)&wbufH[el * RSH + col]     = __floats2half2_rn(ax, ay);
                *(__half2*)&wbufH[el * RSH + col + 2] = __floats2half2_rn(az, aw);
            }
        }
        __syncwarp();

        // ---- layer 2 (fp16 MMA): delta in accD; fp16 gathers in epilogue ----
        int d0 = didx[er0], d1 = didx[er0 + 8];
        int s0 = sidx[er0], s1 = sidx[er0 + 8];
        float accD[8][4];
        zero_acc<8>(accD);
        gemm_h16(wbufH, wp2H, lane, accD);
        __syncwarp();
#pragma unroll
        for (int nt = 0; nt < 8; nt++) {
            int col = nt * 8 + cfr;
            float2 ad0 = __half22float2(*(const __half2*)&g_adst[(size_t)d0 * 64 + col]);
            float2 ad1 = __half22float2(*(const __half2*)&g_adst[(size_t)d1 * 64 + col]);
            float2 as0 = __half22float2(*(const __half2*)&g_asrc[(size_t)s0 * 64 + col]);
            float2 as1 = __half22float2(*(const __half2*)&g_asrc[(size_t)s1 * 64 + col]);
            float2 b = *(const float2*)&sb2[col];
            accD[nt][0] = fmaxf(accD[nt][0] + b.x, 0.f);
            accD[nt][1] = fmaxf(accD[nt][1] + b.y, 0.f);
            accD[nt][2] = fmaxf(accD[nt][2] + b.x, 0.f);
            accD[nt][3] = fmaxf(accD[nt][3] + b.y, 0.f);
            *(__half2*)&wbufH[er0 * RSH + col] =
                __floats2half2_rn(ad0.x - as0.x + accD[nt][0],
                                  ad0.y - as0.y + accD[nt][1]);
            *(__half2*)&wbufH[(er0 + 8) * RSH + col] =
                __floats2half2_rn(ad1.x - as1.x + accD[nt][2],
                                  ad1.y - as1.y + accD[nt][3]);
        }
        __syncwarp();

        // ---- layer 3 (fp16 MMA): h2 = relu(t@attW1+b1) -> wbufH ----
        {
            float acc[8][4];
            zero_acc<8>(acc);
            gemm_h16(wbufH, wa1H, lane, acc);
            __syncwarp();
#pragma unroll
            for (int nt = 0; nt < 8; nt++) {
                int col = nt * 8 + cfr;
                float2 b = *(const float2*)&sab1[col];
                *(__half2*)&wbufH[er0 * RSH + col] =
                    __floats2half2_rn(fmaxf(acc[nt][0] + b.x, 0.f),
                                      fmaxf(acc[nt][1] + b.y, 0.f));
                *(__half2*)&wbufH[(er0 + 8) * RSH + col] =
                    __floats2half2_rn(fmaxf(acc[nt][2] + b.x, 0.f),
                                      fmaxf(acc[nt][3] + b.y, 0.f));
            }
        }
        __syncwarp();

        // ---- layer 4 (fp16 MMA) + m/ex store (fp16) ----
        {
            float acc[8][4];
            zero_acc<8>(acc);
            gemm_h16(wbufH, wa2H, lane, acc);
            __syncwarp();
#pragma unroll
            for (int nt = 0; nt < 8; nt++) {
                int col = nt * 8 + cfr;
                float2 v0 = __half22float2(*(const __half2*)&g_v[(size_t)s0 * 64 + col]);
                float2 v1 = __half22float2(*(const __half2*)&g_v[(size_t)s1 * 64 + col]);
                float2 b = *(const float2*)&sab2[col];
                float e00 = __expf(fmaxf(acc[nt][0] + b.x, 0.f));
                float e01 = __expf(fmaxf(acc[nt][1] + b.y, 0.f));
                float e10 = __expf(fmaxf(acc[nt][2] + b.x, 0.f));
                float e11 = __expf(fmaxf(acc[nt][3] + b.y, 0.f));
                // m -> cols [0,64)
                *(__half2*)&wbufM[er0 * RSM + col] =
                    __floats2half2_rn(e00 * (v0.x + accD[nt][0]),
                                      e01 * (v0.y + accD[nt][1]));
                *(__half2*)&wbufM[(er0 + 8) * RSM + col] =
                    __floats2half2_rn(e10 * (v1.x + accD[nt][2]),
                                      e11 * (v1.y + accD[nt][3]));
                // ex -> cols [64,128)
                *(__half2*)&wbufM[er0 * RSM + 64 + col] = __floats2half2_rn(e00, e01);
                *(__half2*)&wbufM[(er0 + 8) * RSM + 64 + col] = __floats2half2_rn(e10, e11);
            }
        }
        __syncwarp();

        // ---- run-aggregated scatter: one red.v4 warp-op per distinct dst ----
        {
            int i = 0;
            while (i < 16) {
                int d = didx[i];
                float4 a4 = make_float4(0.f, 0.f, 0.f, 0.f);
                int j = i;
                do {
                    const __half2* p = (const __half2*)&wbufM[j * RSM + part];
                    float2 lo = __half22float2(p[0]);
                    float2 hi = __half22float2(p[1]);
                    a4.x += lo.x; a4.y += lo.y; a4.z += hi.x; a4.w += hi.y;
                    j++;
                } while (j < 16 && didx[j] == d);
                float* tgt = (lane < 16)
                    ? &g_num[(size_t)d * 64 + 4 * lane]
                    : &g_den[(size_t)d * 64 + 4 * (lane - 16)];
                red_add4(tgt, a4);
                i = j;
            }
        }
    }
}

// ============================================================================
// final (256 thr): out = relu((num/den)@W_out + b_out) — tf32, unchanged
// ============================================================================
__global__ void __launch_bounds__(256) final_kernel(
    const float* __restrict__ W_out, const float* __restrict__ b_out,
    float* __restrict__ out)
{
    extern __shared__ float sm[];
    float* WoT  = sm;
    float* bo   = sm + 4352;
    float* bufA = sm + 4416;       // -> 13120 floats

    int t = threadIdx.x;
    for (int i = t; i < 4096; i += 256) {
        int k = i >> 6, n = i & 63;
        WoT[n * RS + k] = to_tf32(W_out[i]);
    }
    if (t < 64) bo[t] = b_out[t];
    __syncthreads();

    int w = t >> 5, lane = t & 31;
    int rbase = w * 16;
    int ntiles = (NN + 127) / 128;

    for (int tile = blockIdx.x; tile < ntiles; tile += gridDim.x) {
        int base = tile * 128;
        __syncthreads();
#pragma unroll
        for (int rr = 0; rr < 8; rr++) {
            int i = t + 256 * rr;
            int row = i >> 4, col = (i & 15) * 4;
            int n = base + row;
            float4 v = make_float4(0, 0, 0, 0);
            if (n < NN) {
                float4 nu = *(const float4*)&g_num[(size_t)n * 64 + col];
                float4 de = *(const float4*)&g_den[(size_t)n * 64 + col];
                v.x = to_tf32(nu.x / (de.x + 1e-16f));
                v.y = to_tf32(nu.y / (de.y + 1e-16f));
                v.z = to_tf32(nu.z / (de.z + 1e-16f));
                v.w = to_tf32(nu.w / (de.w + 1e-16f));
            }
            *(float4*)&bufA[(size_t)row * RS + col] = v;
        }
        __syncthreads();

        float acc[8][4];
        zero_acc<8>(acc);
        gemm_ldsm<8, RS>(bufA, WoT, rbase, 0, lane, acc);

        int n0r = base + rbase + (lane >> 2);
#pragma unroll
        for (int nt = 0; nt < 8; nt++) {
            int col = nt * 8 + 2 * (lane & 3);
            float2 b = *(const float2*)&bo[col];
            if (n0r < NN)
                *(float2*)&out[(size_t)n0r * 64 + col] =
                    make_float2(fmaxf(acc[nt][0] + b.x, 0.f),
                                fmaxf(acc[nt][1] + b.y, 0.f));
            if (n0r + 8 < NN)
                *(float2*)&out[(size_t)(n0r + 8) * 64 + col] =
                    make_float2(fmaxf(acc[nt][2] + b.x, 0.f),
                                fmaxf(acc[nt][3] + b.y, 0.f));
        }
    }
}

// ---------------- launch ----------------
extern "C" void kernel_launch(void* const* d_in, const int* in_sizes, int n_in,
                              void* d_out, int out_size)
{
    const float* x      = (const float*)d_in[0];
    const float* pos    = (const float*)d_in[1];
    const int*   ei     = (const int*)d_in[2];
    const float* W_in   = (const float*)d_in[3];
    const float* b_in   = (const float*)d_in[4];
    const float* W_out  = (const float*)d_in[5];
    const float* b_out  = (const float*)d_in[6];
    const float* W_lin  = (const float*)d_in[7];
    const float* W_src  = (const float*)d_in[8];
    const float* W_dst  = (const float*)d_in[9];
    const float* posw1  = (const float*)d_in[10];
    const float* posb1  = (const float*)d_in[11];
    const float* posw2  = (const float*)d_in[12];
    const float* posb2  = (const float*)d_in[13];
    const float* attw1  = (const float*)d_in[14];
    const float* attb1  = (const float*)d_in[15];
    const float* attw2  = (const float*)d_in[16];
    const float* attb2  = (const float*)d_in[17];
    float* out = (float*)d_out;

    const int NP_SMEM = 34880 * 4;   // 136.25 KB
    const int EK_SMEM = 37888 * 4;   // 148 KB -> 1 CTA (576 thr) / SM
    const int FN_SMEM = 13120 * 4;
    cudaFuncSetAttribute(node_prep, cudaFuncAttributeMaxDynamicSharedMemorySize, NP_SMEM);
    cudaFuncSetAttribute(edge_kernel, cudaFuncAttributeMaxDynamicSharedMemorySize, EK_SMEM);
    cudaFuncSetAttribute(final_kernel, cudaFuncAttributeMaxDynamicSharedMemorySize, FN_SMEM);

    const int* srcp = ei;
    const int* dstp = ei + EE;

    zero_kernel<<<1024, 256>>>();
    hist_kernel<<<1024, 256>>>(dstp);
    scan1_kernel<<<SCAN_B, SCAN_T>>>();
    scan2_kernel<<<1, SCAN_T>>>();
    scan3_kernel<<<SCAN_B, SCAN_T>>>();
    scatter_kernel<<<1024, 256>>>(srcp, dstp);
    node_prep<<<148, 256, NP_SMEM>>>(x, W_in, b_in, W_lin, W_src, W_dst);
    edge_kernel<<<148, 576, EK_SMEM>>>(pos,
                                       posw1, posb1, posw2, posb2,
                                       attw1, attb1, attw2, attb2);
    final_kernel<<<444, 256, FN_SMEM>>>(W_out, b_out, out);
}

// round 14
// speedup vs baseline: 2.4570x; 1.0633x over previous
#include <cuda_runtime.h>
#include <cuda_fp16.h>
#include <cstdint>
#include <math.h>

#define NN 100000
#define EE 1600000
#define RSH 72             // fp16 row stride (halves) - all MMA buffers/weights
#define RSM 136            // fp16 m/ex buffer row stride (halves): 128 data + 8 pad
#define SCAN_T 512
#define SCAN_B ((NN + SCAN_T - 1) / SCAN_T)   // 196

// ---------------- device scratch ----------------
__device__ __half g_asrc[NN * 64];
__device__ __half g_adst[NN * 64];
__device__ __half g_v[NN * 64];
__device__ float  g_num[NN * 64];
__device__ float  g_den[NN * 64];
__device__ int    g_cnt[NN];
__device__ int    g_off[NN];
__device__ int    g_cur[NN];
__device__ int    g_bsum[SCAN_B];
__device__ int2   g_sedge[EE];    // packed (src, dst), dst-sorted

// ---------------- helpers ----------------
__device__ __forceinline__ void red_add4(float* p, float4 v) {
    asm volatile("red.global.add.v4.f32 [%0], {%1,%2,%3,%4};"
                 :: "l"(p), "f"(v.x), "f"(v.y), "f"(v.z), "f"(v.w) : "memory");
}
__device__ __forceinline__ void mma_f16(float c[4], unsigned a0, unsigned a1,
                                        unsigned a2, unsigned a3,
                                        unsigned b0, unsigned b1) {
    asm volatile(
        "mma.sync.aligned.m16n8k16.row.col.f32.f16.f16.f32 "
        "{%0,%1,%2,%3},{%4,%5,%6,%7},{%8,%9},{%0,%1,%2,%3};"
        : "+f"(c[0]), "+f"(c[1]), "+f"(c[2]), "+f"(c[3])
        : "r"(a0), "r"(a1), "r"(a2), "r"(a3), "r"(b0), "r"(b1));
}
__device__ __forceinline__ void ldsm4(unsigned addr, unsigned& r0, unsigned& r1,
                                      unsigned& r2, unsigned& r3) {
    asm volatile("ldmatrix.sync.aligned.m8n8.x4.shared.b16 {%0,%1,%2,%3}, [%4];"
                 : "=r"(r0), "=r"(r1), "=r"(r2), "=r"(r3) : "r"(addr));
}

// ---- fp16 ldsm GEMM: A rows [rbase, rbase+16) x 64 halves @RSH, W 64x64 @RSH ----
__device__ __forceinline__ void gemm_h16(const __half* __restrict__ bufH,
                                         const __half* __restrict__ WH,
                                         int rbase, int lane, float acc[8][4]) {
    unsigned aA = (unsigned)__cvta_generic_to_shared(bufH)
                + (unsigned)((rbase + (lane & 15)) * (RSH * 2) + ((lane >> 4) << 4));
    unsigned bA = (unsigned)__cvta_generic_to_shared(WH)
                + (unsigned)(((lane & 7) + ((lane & 16) >> 1)) * (RSH * 2)
                             + ((lane & 8) ? 16 : 0));
#pragma unroll
    for (int kb = 0; kb < 4; kb++) {
        unsigned a0, a1, a2, a3;
        ldsm4(aA + kb * 32, a0, a1, a2, a3);
#pragma unroll
        for (int p = 0; p < 4; p++) {
            unsigned b0, b1, b2, b3;
            ldsm4(bA + (unsigned)(p * 16 * RSH * 2 + kb * 32), b0, b1, b2, b3);
            mma_f16(acc[2 * p],     a0, a1, a2, a3, b0, b1);
            mma_f16(acc[2 * p + 1], a0, a1, a2, a3, b2, b3);
        }
    }
}

__device__ __forceinline__ void zero_acc8(float acc[8][4]) {
#pragma unroll
    for (int nt = 0; nt < 8; nt++)
#pragma unroll
        for (int j = 0; j < 4; j++) acc[nt][j] = 0.f;
}

// ---------------- init + sort chain ----------------
__global__ void zero_kernel() {
    int i = blockIdx.x * blockDim.x + threadIdx.x;
    int stride = gridDim.x * blockDim.x;
    float4 z = make_float4(0.f, 0.f, 0.f, 0.f);
    for (int j = i; j < NN * 64 / 4; j += stride) {
        ((float4*)g_num)[j] = z;
        ((float4*)g_den)[j] = z;
    }
    for (int j = i; j < NN; j += stride) g_cnt[j] = 0;
}

__global__ void hist_kernel(const int* __restrict__ dst) {
    int i = blockIdx.x * blockDim.x + threadIdx.x;
    int stride = gridDim.x * blockDim.x;
    for (; i < EE; i += stride) atomicAdd(&g_cnt[dst[i]], 1);
}

__global__ void scan1_kernel() {
    __shared__ int s[SCAN_T];
    int tid = threadIdx.x;
    int i = blockIdx.x * SCAN_T + tid;
    int v = (i < NN) ? g_cnt[i] : 0;
    s[tid] = v;
    __syncthreads();
#pragma unroll
    for (int off = 1; off < SCAN_T; off <<= 1) {
        int t2 = (tid >= off) ? s[tid - off] : 0;
        __syncthreads();
        s[tid] += t2;
        __syncthreads();
    }
    if (i < NN) g_off[i] = s[tid] - v;
    if (tid == SCAN_T - 1) g_bsum[blockIdx.x] = s[SCAN_T - 1];
}

__global__ void scan2_kernel() {
    __shared__ int s[SCAN_T];
    int tid = threadIdx.x;
    int v = (tid < SCAN_B) ? g_bsum[tid] : 0;
    s[tid] = v;
    __syncthreads();
#pragma unroll
    for (int off = 1; off < SCAN_T; off <<= 1) {
        int t2 = (tid >= off) ? s[tid - off] : 0;
        __syncthreads();
        s[tid] += t2;
        __syncthreads();
    }
    if (tid < SCAN_B) g_bsum[tid] = s[tid] - v;
}

__global__ void scan3_kernel() {
    int i = blockIdx.x * SCAN_T + threadIdx.x;
    if (i < NN) {
        int o = g_off[i] + g_bsum[blockIdx.x];
        g_off[i] = o;
        g_cur[i] = o;
    }
}

__global__ void scatter_kernel(const int* __restrict__ src,
                               const int* __restrict__ dst) {
    int i = blockIdx.x * blockDim.x + threadIdx.x;
    int stride = gridDim.x * blockDim.x;
    for (; i < EE; i += stride) {
        int d = dst[i];
        int p = atomicAdd(&g_cur[d], 1);
        g_sedge[p] = make_int2(src[i], d);
    }
}

// ============================================================================
// node_prep (256 thr, 128-node tiles) — fp16 MMA, fp16 outputs
// ============================================================================
__global__ void __launch_bounds__(256) node_prep(
    const float* __restrict__ x,
    const float* __restrict__ W_in, const float* __restrict__ b_in,
    const float* __restrict__ W_lin, const float* __restrict__ W_src,
    const float* __restrict__ W_dst)
{
    extern __shared__ float sm[];
    __half* WinH = (__half*)sm;            // 4608 halves each
    __half* WsH  = WinH + 4608;
    __half* WdH  = WinH + 9216;
    __half* WlH  = WinH + 13824;           // ends at 18432 halves = 9216 floats
    float*  bin  = sm + 9216;              // 64
    __half* bufA = (__half*)(sm + 9280);   // 128*RSH = 9216 halves = 4608 floats
    __half* bufB = bufA + 9216;            // 4608 floats -> total 18496 floats

    int t = threadIdx.x;
    for (int i = t; i < 4096; i += 256) {
        int k = i >> 6, n = i & 63;
        WinH[n * RSH + k] = __float2half_rn(W_in[i]);
        WsH[n * RSH + k]  = __float2half_rn(W_src[i]);
        WdH[n * RSH + k]  = __float2half_rn(W_dst[i]);
        WlH[n * RSH + k]  = __float2half_rn(W_lin[i]);
    }
    if (t < 64) bin[t] = b_in[t];
    __syncthreads();

    int w = t >> 5, lane = t & 31;
    int rbase = w * 16;
    int er0 = rbase + (lane >> 2);
    int cfr = 2 * (lane & 3);
    int ntiles = (NN + 127) / 128;

    for (int tile = blockIdx.x; tile < ntiles; tile += gridDim.x) {
        int base = tile * 128;
        __syncthreads();
        // stage x tile -> fp16
#pragma unroll
        for (int rr = 0; rr < 8; rr++) {
            int i = t + 256 * rr;
            int row = i >> 4, col = (i & 15) * 4;
            int n = base + row;
            float4 v = make_float4(0, 0, 0, 0);
            if (n < NN) v = *(const float4*)&x[(size_t)n * 64 + col];
            __half2 h0 = __floats2half2_rn(v.x, v.y);
            __half2 h1 = __floats2half2_rn(v.z, v.w);
            *(__half2*)&bufA[(size_t)row * RSH + col] = h0;
            *(__half2*)&bufA[(size_t)row * RSH + col + 2] = h1;
        }
        __syncthreads();

        // h = relu(x@W_in + b) -> bufB (fp16)
        {
            float acc[8][4];
            zero_acc8(acc);
            gemm_h16(bufA, WinH, rbase, lane, acc);
#pragma unroll
            for (int nt = 0; nt < 8; nt++) {
                int col = nt * 8 + cfr;
                float2 b = *(const float2*)&bin[col];
                *(__half2*)&bufB[(size_t)er0 * RSH + col] =
                    __floats2half2_rn(fmaxf(acc[nt][0] + b.x, 0.f),
                                      fmaxf(acc[nt][1] + b.y, 0.f));
                *(__half2*)&bufB[(size_t)(er0 + 8) * RSH + col] =
                    __floats2half2_rn(fmaxf(acc[nt][2] + b.x, 0.f),
                                      fmaxf(acc[nt][3] + b.y, 0.f));
            }
        }
        __syncthreads();

        // three output GEMMs -> fp16 global
        const __half* WHs[3] = {WsH, WdH, WlH};
        __half* outs[3] = {g_asrc, g_adst, g_v};
        int n0r = base + er0;
#pragma unroll
        for (int p = 0; p < 3; p++) {
            float acc[8][4];
            zero_acc8(acc);
            gemm_h16(bufB, WHs[p], rbase, lane, acc);
#pragma unroll
            for (int nt = 0; nt < 8; nt++) {
                int col = nt * 8 + cfr;
                if (n0r < NN)
                    *(__half2*)&outs[p][(size_t)n0r * 64 + col] =
                        __floats2half2_rn(acc[nt][0], acc[nt][1]);
                if (n0r + 8 < NN)
                    *(__half2*)&outs[p][(size_t)(n0r + 8) * 64 + col] =
                        __floats2half2_rn(acc[nt][2], acc[nt][3]);
            }
        }
    }
}

// ============================================================================
// edge kernel: warp-autonomous 16-edge tiles, dst-sorted (int2), fp16 MMA,
// fp16 gathers + m/ex staging, run-aggregated scatter. 576 thr, 1 CTA/SM.
// ============================================================================
__global__ void __launch_bounds__(576, 1) edge_kernel(
    const float* __restrict__ pos,
    const float* __restrict__ posw1, const float* __restrict__ posb1,
    const float* __restrict__ posw2, const float* __restrict__ posb2,
    const float* __restrict__ attw1, const float* __restrict__ attb1,
    const float* __restrict__ attw2, const float* __restrict__ attb2)
{
    extern __shared__ float sm[];
    float* sw1  = sm;              // 192
    float* sb1  = sm + 192;        // 64
    float* sb2  = sm + 256;        // 64
    float* sab1 = sm + 320;        // 64
    float* sab2 = sm + 384;        // 64 -> 448
    __half* WhBase = (__half*)(sm + 448);
    __half* wp2H = WhBase;
    __half* wa1H = WhBase + 4608;
    __half* wa2H = WhBase + 9216;  // ends at 7360 floats

    int t = threadIdx.x;
    int wid = t >> 5, lane = t & 31;
    float*  wbase = sm + 7360 + wid * 1696;
    __half* wbufM = (__half*)wbase;            // 16*RSM = 2176 halves
    __half* wbufH = (__half*)(wbase + 1088);   // 16*RSH = 1152 halves
    int*    sidx  = (int*)(wbase + 1664);      // 16
    int*    didx  = sidx + 16;                 // 16 -> total 37888 floats

    for (int i = t; i < 4096; i += 576) {
        int k = i >> 6, n = i & 63;
        wp2H[n * RSH + k] = __float2half_rn(posw2[i]);
        wa1H[n * RSH + k] = __float2half_rn(attw1[i]);
        wa2H[n * RSH + k] = __float2half_rn(attw2[i]);
    }
    if (t < 192) sw1[t] = posw1[t];
    if (t < 64) { sb1[t] = posb1[t]; sb2[t] = posb2[t];
                  sab1[t] = attb1[t]; sab2[t] = attb2[t]; }
    __syncthreads();

    int el  = lane >> 1;             // row-layout: local edge 0..15
    int c0r = (lane & 1) * 32;       // row-layout: 32 channels per lane
    int er0 = lane >> 2;             // frag rows er0, er0+8
    int cfr = 2 * (lane & 3);        // frag col offset
    int part = (lane < 16) ? 4 * lane : 64 + 4 * (lane - 16);  // reduce slot

    const int nwt = gridDim.x * 18;
    for (int wt = blockIdx.x * 18 + wid; wt < EE / 16; wt += nwt) {
        int ebase = wt * 16;
        __syncwarp();
        if (lane < 16) {
            int2 e = g_sedge[ebase + lane];
            sidx[lane] = e.x;
            didx[lane] = e.y;
        }
        __syncwarp();

        int sE = sidx[el], dE = didx[el];
        // ---- layer 1 (K=3, scalar): h1 -> wbufH (fp16) ----
        {
            float p0 = __ldg(pos + dE * 3 + 0) - __ldg(pos + sE * 3 + 0);
            float p1 = __ldg(pos + dE * 3 + 1) - __ldg(pos + sE * 3 + 1);
            float p2 = __ldg(pos + dE * 3 + 2) - __ldg(pos + sE * 3 + 2);
#pragma unroll
            for (int j = 0; j < 8; j++) {
                int col = c0r + 4 * j;
                float4 b   = *(float4*)&sb1[col];
                float4 w0  = *(float4*)&sw1[col];
                float4 w1r = *(float4*)&sw1[64 + col];
                float4 w2r = *(float4*)&sw1[128 + col];
                float ax = fmaxf(fmaf(p2, w2r.x, fmaf(p1, w1r.x, fmaf(p0, w0.x, b.x))), 0.f);
                float ay = fmaxf(fmaf(p2, w2r.y, fmaf(p1, w1r.y, fmaf(p0, w0.y, b.y))), 0.f);
                float az = fmaxf(fmaf(p2, w2r.z, fmaf(p1, w1r.z, fmaf(p0, w0.z, b.z))), 0.f);
                float aw = fmaxf(fmaf(p2, w2r.w, fmaf(p1, w1r.w, fmaf(p0, w0.w, b.w))), 0.f);
                *(__half2*)&wbufH[el * RSH + col]     = __floats2half2_rn(ax, ay);
                *(__half2*)&wbufH[el * RSH + col + 2] = __floats2half2_rn(az, aw);
            }
        }
        __syncwarp();

        // ---- layer 2 (fp16 MMA): delta in accD; fp16 gathers in epilogue ----
        int d0 = didx[er0], d1 = didx[er0 + 8];
        int s0 = sidx[er0], s1 = sidx[er0 + 8];
        float accD[8][4];
        zero_acc8(accD);
        gemm_h16(wbufH, wp2H, 0, lane, accD);
        __syncwarp();
#pragma unroll
        for (int nt = 0; nt < 8; nt++) {
            int col = nt * 8 + cfr;
            float2 ad0 = __half22float2(*(const __half2*)&g_adst[(size_t)d0 * 64 + col]);
            float2 ad1 = __half22float2(*(const __half2*)&g_adst[(size_t)d1 * 64 + col]);
            float2 as0 = __half22float2(*(const __half2*)&g_asrc[(size_t)s0 * 64 + col]);
            float2 as1 = __half22float2(*(const __half2*)&g_asrc[(size_t)s1 * 64 + col]);
            float2 b = *(const float2*)&sb2[col];
            accD[nt][0] = fmaxf(accD[nt][0] + b.x, 0.f);
            accD[nt][1] = fmaxf(accD[nt][1] + b.y, 0.f);
            accD[nt][2] = fmaxf(accD[nt][2] + b.x, 0.f);
            accD[nt][3] = fmaxf(accD[nt][3] + b.y, 0.f);
            *(__half2*)&wbufH[er0 * RSH + col] =
                __floats2half2_rn(ad0.x - as0.x + accD[nt][0],
                                  ad0.y - as0.y + accD[nt][1]);
            *(__half2*)&wbufH[(er0 + 8) * RSH + col] =
                __floats2half2_rn(ad1.x - as1.x + accD[nt][2],
                                  ad1.y - as1.y + accD[nt][3]);
        }
        __syncwarp();

        // ---- layer 3 (fp16 MMA): h2 = relu(t@attW1+b1) -> wbufH ----
        {
            float acc[8][4];
            zero_acc8(acc);
            gemm_h16(wbufH, wa1H, 0, lane, acc);
            __syncwarp();
#pragma unroll
            for (int nt = 0; nt < 8; nt++) {
                int col = nt * 8 + cfr;
                float2 b = *(const float2*)&sab1[col];
                *(__half2*)&wbufH[er0 * RSH + col] =
                    __floats2half2_rn(fmaxf(acc[nt][0] + b.x, 0.f),
                                      fmaxf(acc[nt][1] + b.y, 0.f));
                *(__half2*)&wbufH[(er0 + 8) * RSH + col] =
                    __floats2half2_rn(fmaxf(acc[nt][2] + b.x, 0.f),
                                      fmaxf(acc[nt][3] + b.y, 0.f));
            }
        }
        __syncwarp();

        // ---- layer 4 (fp16 MMA) + m/ex store (fp16) ----
        {
            float acc[8][4];
            zero_acc8(acc);
            gemm_h16(wbufH, wa2H, 0, lane, acc);
            __syncwarp();
#pragma unroll
            for (int nt = 0; nt < 8; nt++) {
                int col = nt * 8 + cfr;
                float2 v0 = __half22float2(*(const __half2*)&g_v[(size_t)s0 * 64 + col]);
                float2 v1 = __half22float2(*(const __half2*)&g_v[(size_t)s1 * 64 + col]);
                float2 b = *(const float2*)&sab2[col];
                float e00 = __expf(fmaxf(acc[nt][0] + b.x, 0.f));
                float e01 = __expf(fmaxf(acc[nt][1] + b.y, 0.f));
                float e10 = __expf(fmaxf(acc[nt][2] + b.x, 0.f));
                float e11 = __expf(fmaxf(acc[nt][3] + b.y, 0.f));
                // m -> cols [0,64)
                *(__half2*)&wbufM[er0 * RSM + col] =
                    __floats2half2_rn(e00 * (v0.x + accD[nt][0]),
                                      e01 * (v0.y + accD[nt][1]));
                *(__half2*)&wbufM[(er0 + 8) * RSM + col] =
                    __floats2half2_rn(e10 * (v1.x + accD[nt][2]),
                                      e11 * (v1.y + accD[nt][3]));
                // ex -> cols [64,128)
                *(__half2*)&wbufM[er0 * RSM + 64 + col] = __floats2half2_rn(e00, e01);
                *(__half2*)&wbufM[(er0 + 8) * RSM + 64 + col] = __floats2half2_rn(e10, e11);
            }
        }
        __syncwarp();

        // ---- run-aggregated scatter: one red.v4 warp-op per distinct dst ----
        {
            int i = 0;
            while (i < 16) {
                int d = didx[i];
                float4 a4 = make_float4(0.f, 0.f, 0.f, 0.f);
                int j = i;
                do {
                    const __half2* p = (const __half2*)&wbufM[j * RSM + part];
                    float2 lo = __half22float2(p[0]);
                    float2 hi = __half22float2(p[1]);
                    a4.x += lo.x; a4.y += lo.y; a4.z += hi.x; a4.w += hi.y;
                    j++;
                } while (j < 16 && didx[j] == d);
                float* tgt = (lane < 16)
                    ? &g_num[(size_t)d * 64 + 4 * lane]
                    : &g_den[(size_t)d * 64 + 4 * (lane - 16)];
                red_add4(tgt, a4);
                i = j;
            }
        }
    }
}

// ============================================================================
// final (256 thr): out = relu((num/den)@W_out + b_out) — fp16 MMA
// ============================================================================
__global__ void __launch_bounds__(256) final_kernel(
    const float* __restrict__ W_out, const float* __restrict__ b_out,
    float* __restrict__ out)
{
    extern __shared__ float sm[];
    __half* WoH  = (__half*)sm;            // 4608 halves = 2304 floats
    float*  bo   = sm + 2304;              // 64
    __half* bufA = (__half*)(sm + 2368);   // 9216 halves = 4608 floats -> 6976 floats

    int t = threadIdx.x;
    for (int i = t; i < 4096; i += 256) {
        int k = i >> 6, n = i & 63;
        WoH[n * RSH + k] = __float2half_rn(W_out[i]);
    }
    if (t < 64) bo[t] = b_out[t];
    __syncthreads();

    int w = t >> 5, lane = t & 31;
    int rbase = w * 16;
    int er0 = rbase + (lane >> 2);
    int cfr = 2 * (lane & 3);
    int ntiles = (NN + 127) / 128;

    for (int tile = blockIdx.x; tile < ntiles; tile += gridDim.x) {
        int base = tile * 128;
        __syncthreads();
#pragma unroll
        for (int rr = 0; rr < 8; rr++) {
            int i = t + 256 * rr;
            int row = i >> 4, col = (i & 15) * 4;
            int n = base + row;
            float4 v = make_float4(0, 0, 0, 0);
            if (n < NN) {
                float4 nu = *(const float4*)&g_num[(size_t)n * 64 + col];
                float4 de = *(const float4*)&g_den[(size_t)n * 64 + col];
                v.x = nu.x / (de.x + 1e-16f);
                v.y = nu.y / (de.y + 1e-16f);
                v.z = nu.z / (de.z + 1e-16f);
                v.w = nu.w / (de.w + 1e-16f);
            }
            *(__half2*)&bufA[(size_t)row * RSH + col] = __floats2half2_rn(v.x, v.y);
            *(__half2*)&bufA[(size_t)row * RSH + col + 2] = __floats2half2_rn(v.z, v.w);
        }
        __syncthreads();

        float acc[8][4];
        zero_acc8(acc);
        gemm_h16(bufA, WoH, rbase, lane, acc);

        int n0r = base + er0;
#pragma unroll
        for (int nt = 0; nt < 8; nt++) {
            int col = nt * 8 + cfr;
            float2 b = *(const float2*)&bo[col];
            if (n0r < NN)
                *(float2*)&out[(size_t)n0r * 64 + col] =
                    make_float2(fmaxf(acc[nt][0] + b.x, 0.f),
                                fmaxf(acc[nt][1] + b.y, 0.f));
            if (n0r + 8 < NN)
                *(float2*)&out[(size_t)(n0r + 8) * 64 + col] =
                    make_float2(fmaxf(acc[nt][2] + b.x, 0.f),
                                fmaxf(acc[nt][3] + b.y, 0.f));
        }
    }
}

// ---------------- launch ----------------
extern "C" void kernel_launch(void* const* d_in, const int* in_sizes, int n_in,
                              void* d_out, int out_size)
{
    const float* x      = (const float*)d_in[0];
    const float* pos    = (const float*)d_in[1];
    const int*   ei     = (const int*)d_in[2];
    const float* W_in   = (const float*)d_in[3];
    const float* b_in   = (const float*)d_in[4];
    const float* W_out  = (const float*)d_in[5];
    const float* b_out  = (const float*)d_in[6];
    const float* W_lin  = (const float*)d_in[7];
    const float* W_src  = (const float*)d_in[8];
    const float* W_dst  = (const float*)d_in[9];
    const float* posw1  = (const float*)d_in[10];
    const float* posb1  = (const float*)d_in[11];
    const float* posw2  = (const float*)d_in[12];
    const float* posb2  = (const float*)d_in[13];
    const float* attw1  = (const float*)d_in[14];
    const float* attb1  = (const float*)d_in[15];
    const float* attw2  = (const float*)d_in[16];
    const float* attb2  = (const float*)d_in[17];
    float* out = (float*)d_out;

    const int NP_SMEM = 18496 * 4;   // 72.25 KB
    const int EK_SMEM = 37888 * 4;   // 148 KB -> 1 CTA (576 thr) / SM
    const int FN_SMEM = 6976 * 4;    // 27.25 KB
    cudaFuncSetAttribute(node_prep, cudaFuncAttributeMaxDynamicSharedMemorySize, NP_SMEM);
    cudaFuncSetAttribute(edge_kernel, cudaFuncAttributeMaxDynamicSharedMemorySize, EK_SMEM);
    cudaFuncSetAttribute(final_kernel, cudaFuncAttributeMaxDynamicSharedMemorySize, FN_SMEM);

    const int* srcp = ei;
    const int* dstp = ei + EE;

    zero_kernel<<<1024, 256>>>();
    hist_kernel<<<1024, 256>>>(dstp);
    scan1_kernel<<<SCAN_B, SCAN_T>>>();
    scan2_kernel<<<1, SCAN_T>>>();
    scan3_kernel<<<SCAN_B, SCAN_T>>>();
    scatter_kernel<<<1024, 256>>>(srcp, dstp);
    node_prep<<<296, 256, NP_SMEM>>>(x, W_in, b_in, W_lin, W_src, W_dst);
    edge_kernel<<<148, 576, EK_SMEM>>>(pos,
                                       posw1, posb1, posw2, posb2,
                                       attw1, attb1, attw2, attb2);
    final_kernel<<<444, 256, FN_SMEM>>>(W_out, b_out, out);
}